// round 12
// baseline (speedup 1.0000x reference)
#include <cuda_runtime.h>
#include <cuda_bf16.h>
#include <cstdint>

// Shapes (fixed per problem)
#define BB 8
#define TT 2048
#define CC 768
#define WDIM 512
#define TD 384
#define CD 3072
#define ROWS (BB * TT)          // 16384

// weight pack offsets (elements), layout (K, N) n-contiguous
#define OFF_G12 0               // fused g1|g2, (768, 1536)
#define OFF_M1 1179648
#define OFF_M2 1327104
#define OFF_GS 1474560
#define OFF_MS 3833856
#define OFF_R1 5013504
#define OFF_R2 5603328
#define WTOT   5898240

// bias pack offsets
#define BI_G12 0
#define BI_GS  1536
#define BI_R1  (1536 + CD)

typedef __nv_bfloat16 bf16;

// ---------------- scratch (device globals; no allocation allowed) ----------
__device__ float BUF_XLN[ROWS * CC];
__device__ float BUF_X2 [ROWS * CC];
__device__ float BUF_S1 [BB * TD];
__device__ float BUF_S2 [BB * TD];
__device__ float BUF_SS [BB * (CD/2)];
__device__ float BUF_BI [1536 + CD + CC];

__device__ bf16 S_XLNh[ROWS * CC],      S_XLNl[ROWS * CC];
__device__ bf16 S_ACTh[ROWS * (CD/2)],  S_ACTl[ROWS * (CD/2)];
__device__ bf16 S_A1h [ROWS * TD],      S_A1l [ROWS * TD];
__device__ bf16 S_A2h [ROWS * TD],      S_A2l [ROWS * TD];
__device__ bf16 S_H1h [BB * TD * TT],   S_H1l [BB * TD * TT];   // (b,d,t)
__device__ bf16 S_H2h [ROWS * TD],      S_H2l [ROWS * TD];      // (b,t,d)
__device__ bf16 S_MIXh[BB * TD * CC],   S_MIXl[BB * TD * CC];   // (b,d,c)
__device__ bf16 S_X3h [ROWS * CC],      S_X3l [ROWS * CC];
__device__ bf16 S_Wh  [WTOT],           S_Wl  [WTOT];

// ---------------- helpers ---------------------------------------------------
__device__ __forceinline__ float gelu_f(float v) {
    return 0.5f * v * (1.0f + erff(v * 0.70710678118654752f));
}
__device__ __forceinline__ void split_bf16(float v, bf16& h, bf16& l) {
    h = __float2bfloat16_rn(v);
    l = __float2bfloat16_rn(v - __bfloat162float(h));
}
__device__ __forceinline__ void cp16(void* smem, const void* gmem) {
    uint32_t s = (uint32_t)__cvta_generic_to_shared(smem);
    asm volatile("cp.async.cg.shared.global [%0], [%1], 16;" :: "r"(s), "l"(gmem));
}
__device__ __forceinline__ void cp_commit() { asm volatile("cp.async.commit_group;"); }

__device__ __forceinline__ void ldsm4(uint32_t* r, const void* p) {
    uint32_t a = (uint32_t)__cvta_generic_to_shared(p);
    asm volatile("ldmatrix.sync.aligned.m8n8.x4.shared.b16 {%0,%1,%2,%3}, [%4];"
                 : "=r"(r[0]), "=r"(r[1]), "=r"(r[2]), "=r"(r[3]) : "r"(a));
}
__device__ __forceinline__ void ldsm4t(uint32_t* r, const void* p) {
    uint32_t a = (uint32_t)__cvta_generic_to_shared(p);
    asm volatile("ldmatrix.sync.aligned.m8n8.x4.trans.shared.b16 {%0,%1,%2,%3}, [%4];"
                 : "=r"(r[0]), "=r"(r[1]), "=r"(r[2]), "=r"(r[3]) : "r"(a));
}
__device__ __forceinline__ void mma_bf16(float* d, const uint32_t* a, const uint32_t* b) {
    asm volatile(
        "mma.sync.aligned.m16n8k16.row.col.f32.bf16.bf16.f32 "
        "{%0,%1,%2,%3}, {%4,%5,%6,%7}, {%8,%9}, {%0,%1,%2,%3};"
        : "+f"(d[0]), "+f"(d[1]), "+f"(d[2]), "+f"(d[3])
        : "r"(a[0]), "r"(a[1]), "r"(a[2]), "r"(a[3]), "r"(b[0]), "r"(b[1]));
}

// ---------------- LayerNorm (+ bf16 split output) ----------------------------
__global__ void ln_split_kernel(const float* __restrict__ x,
                                const float* __restrict__ g,
                                const float* __restrict__ b,
                                float* __restrict__ yf,
                                bf16* __restrict__ yh,
                                bf16* __restrict__ yl, int C) {
    __shared__ float red[2][8];
    long row = blockIdx.x;
    const float* xr = x + row * C;
    float s = 0.f, s2 = 0.f;
    for (int c = threadIdx.x; c < C; c += blockDim.x) {
        float v = xr[c];
        s += v; s2 += v * v;
    }
    #pragma unroll
    for (int o = 16; o; o >>= 1) {
        s  += __shfl_xor_sync(0xFFFFFFFFu, s,  o);
        s2 += __shfl_xor_sync(0xFFFFFFFFu, s2, o);
    }
    int w = threadIdx.x >> 5, l = threadIdx.x & 31;
    if (l == 0) { red[0][w] = s; red[1][w] = s2; }
    __syncthreads();
    if (threadIdx.x < 32) {
        s  = (l < 8) ? red[0][l] : 0.f;
        s2 = (l < 8) ? red[1][l] : 0.f;
        #pragma unroll
        for (int o = 4; o; o >>= 1) {
            s  += __shfl_xor_sync(0xFFFFFFFFu, s,  o);
            s2 += __shfl_xor_sync(0xFFFFFFFFu, s2, o);
        }
        if (l == 0) { red[0][0] = s; red[1][0] = s2; }
    }
    __syncthreads();
    float mu  = red[0][0] / C;
    float var = red[1][0] / C - mu * mu;
    float inv = rsqrtf(var + 1e-6f);
    for (int c = threadIdx.x; c < C; c += blockDim.x) {
        float v = (xr[c] - mu) * inv * g[c] + b[c];
        if (yf) yf[row * C + c] = v;
        bf16 h, lo;
        split_bf16(v, h, lo);
        yh[row * C + c] = h;
        yl[row * C + c] = lo;
    }
}

// ---------------- plain weight -> hi/lo bf16 split ---------------------------
__global__ void cvt_split_kernel(const float4* __restrict__ in,
                                 bf16* __restrict__ oh,
                                 bf16* __restrict__ ol, int n4) {
    int idx = blockIdx.x * blockDim.x + threadIdx.x;
    if (idx >= n4) return;
    float4 v = in[idx];
    bf16 h[4], l[4];
    split_bf16(v.x, h[0], l[0]); split_bf16(v.y, h[1], l[1]);
    split_bf16(v.z, h[2], l[2]); split_bf16(v.w, h[3], l[3]);
    *(__nv_bfloat162*)(oh + 4L*idx    ) = __nv_bfloat162(h[0], h[1]);
    *(__nv_bfloat162*)(oh + 4L*idx + 2) = __nv_bfloat162(h[2], h[3]);
    *(__nv_bfloat162*)(ol + 4L*idx    ) = __nv_bfloat162(l[0], l[1]);
    *(__nv_bfloat162*)(ol + 4L*idx + 2) = __nv_bfloat162(l[2], l[3]);
}

// ---------------- GLU weight pack: interleave (a_j, gate_j) columns ----------
__global__ void glu_pack_w(const float* __restrict__ W,
                           const float* __restrict__ b,
                           bf16* __restrict__ oh, bf16* __restrict__ ol,
                           float* __restrict__ biasI, long total, int H,
                           int ldout, int coloff) {
    long idx = (long)blockIdx.x * blockDim.x + threadIdx.x;
    if (idx >= total) return;
    long k = idx / H;
    int  n = (int)(idx - k * H);
    int  src = (n & 1) ? (n >> 1) + (H >> 1) : (n >> 1);
    bf16 h, l;
    split_bf16(W[k * H + src], h, l);
    const long o = k * ldout + coloff + n;
    oh[o] = h;
    ol[o] = l;
    if (k == 0) biasI[coloff + n] = b[src];
}

// ---------------- style-projection: block (32,32), k-split 16 ----------------
__global__ void style_s_kernel(const float* __restrict__ w,
                               const float* __restrict__ sW,
                               const float* __restrict__ sb,
                               float* __restrict__ out, int sel, int N) {
    __shared__ float red[32][33];
    const int b = blockIdx.y;
    const int n = blockIdx.x * 32 + threadIdx.x;
    const int ky = threadIdx.y;
    const float* wr = w + b * (2 * WDIM) + sel * WDIM;
    float acc = 0.f;
    #pragma unroll
    for (int k = ky * 16; k < ky * 16 + 16; k++)
        acc += wr[k] * sW[(long)k * N + n];
    red[ky][threadIdx.x] = acc;
    __syncthreads();
    if (ky == 0) {
        float s = sb[n];
        #pragma unroll
        for (int i = 0; i < 32; i++) s += red[i][threadIdx.x];
        out[b * N + n] = s;
    }
}

// ---------------- bf16x3 mma.sync GEMM, tiled BMxBNx32 -----------------------
// C(M,N) = (Ah+Al)(M,K) @ (Bh+Bl)(K,N)  (lo*lo dropped)
// A k-contig (lda), B n-contig (ldb). Warp tile 64x64, 3-stage cp.async.
#define ASTR 40

template <int BM, int BN, bool GLU, bool GLUPAIR, bool GELU, bool SPLIT,
          bool TRANSO, bool FP32O>
__global__ __launch_bounds__((BM/64)*(BN/64)*32, (BM==128 && BN==128) ? 2 : 1)
void gemm_v5(
    const bf16* __restrict__ Ah, const bf16* __restrict__ Al,
    const bf16* __restrict__ Bh, const bf16* __restrict__ Bl,
    const float* __restrict__ bias,
    const float* __restrict__ styleS, const float* __restrict__ styleS2,
    const float* __restrict__ res,
    float* __restrict__ Cf, bf16* __restrict__ Ch, bf16* __restrict__ Cl,
    bf16* __restrict__ Ch2, bf16* __restrict__ Cl2,
    int N, int K, int lda, int ldb,
    long sA, long sB, long sC, long sRes)
{
    constexpr int WN      = BN / 64;
    constexpr int NWARP   = (BM/64) * WN;
    constexpr int THREADS = NWARP * 32;
    constexpr int BSTRN   = BN + 8;
    constexpr int A_B     = BM * ASTR * 2;     // bytes per hi/lo A array
    constexpr int B_B     = 32 * BSTRN * 2;
    constexpr int STG     = 2 * A_B + 2 * B_B;
    constexpr int CH      = BN / 8;            // 8-elem chunks per B row

    extern __shared__ char smem[];

    const int z = blockIdx.z;
    const bf16* Agh = Ah + (long)z * sA;
    const bf16* Agl = Al + (long)z * sA;
    const bf16* Bgh = Bh + (long)z * sB;
    const bf16* Bgl = Bl + (long)z * sB;
    const float* resp = res ? res + (long)z * sRes : nullptr;

    const int m0 = blockIdx.y * BM, n0 = blockIdx.x * BN;
    const int tid = threadIdx.x;
    const int lane = tid & 31, wid = tid >> 5;
    const int wm = wid / WN, wn = wid % WN;    // warp tile 64x64
    const int lr = lane >> 2, lc = lane & 3;

    const int aoffL = (lane & 15) * ASTR + ((lane >> 4) << 3);
    const int boffC = ((lane >> 4) << 3);

    float acc[4][8][4];
    #pragma unroll
    for (int i = 0; i < 4; i++)
        #pragma unroll
        for (int j = 0; j < 8; j++) {
            acc[i][j][0] = 0.f; acc[i][j][1] = 0.f;
            acc[i][j][2] = 0.f; acc[i][j][3] = 0.f;
        }

    auto loadStage = [&](int st, int k0) {
        char* base = smem + st * STG;
        bf16* ah = (bf16*)(base);
        bf16* al = (bf16*)(base + A_B);
        bf16* bh = (bf16*)(base + 2 * A_B);
        bf16* bl = (bf16*)(base + 2 * A_B + B_B);
        #pragma unroll
        for (int i = tid; i < BM * 4; i += THREADS) {
            const int r = i >> 2, c = i & 3;
            const long go = (long)(m0 + r) * lda + k0 + c * 8;
            const int so = r * ASTR + c * 8;
            cp16(ah + so, Agh + go);
            cp16(al + so, Agl + go);
        }
        #pragma unroll
        for (int i = tid; i < 32 * CH; i += THREADS) {
            const int r = i / CH, c = i % CH;
            const long go = (long)(k0 + r) * ldb + n0 + c * 8;
            const int so = r * BSTRN + c * 8;
            cp16(bh + so, Bgh + go);
            cp16(bl + so, Bgl + go);
        }
        cp_commit();
    };

    const int NST = K >> 5;
    loadStage(0, 0);
    if (NST > 1) loadStage(1, 32);

    for (int it = 0; it < NST; it++) {
        const int st = it % 3;
        if (it + 2 <= NST) asm volatile("cp.async.wait_group 1;" ::: "memory");
        else               asm volatile("cp.async.wait_group 0;" ::: "memory");
        __syncthreads();
        if (it + 2 < NST) loadStage((it + 2) % 3, (it + 2) << 5);

        char* base = smem + st * STG;
        const bf16* ah = (const bf16*)(base);
        const bf16* al = (const bf16*)(base + A_B);
        const bf16* bh = (const bf16*)(base + 2 * A_B);
        const bf16* bl = (const bf16*)(base + 2 * A_B + B_B);

        #pragma unroll
        for (int ks = 0; ks < 2; ks++) {
            uint32_t fAh[4][4], fAl[4][4];
            const int aoff = aoffL + ks * 16;
            #pragma unroll
            for (int mt = 0; mt < 4; mt++) {
                const int mb = (wm * 64 + mt * 16) * ASTR + aoff;
                ldsm4(fAh[mt], ah + mb);
                ldsm4(fAl[mt], al + mb);
            }
            const int brow = (ks * 16 + (lane & 15)) * BSTRN + boffC;
            #pragma unroll
            for (int ph = 0; ph < 2; ph++) {
                uint32_t fBh[4][2], fBl[4][2];
                #pragma unroll
                for (int p = 0; p < 2; p++) {
                    const int nb = brow + wn * 64 + ph * 32 + p * 16;
                    uint32_t r[4];
                    ldsm4t(r, bh + nb);
                    fBh[2*p][0] = r[0]; fBh[2*p][1] = r[1];
                    fBh[2*p+1][0] = r[2]; fBh[2*p+1][1] = r[3];
                    ldsm4t(r, bl + nb);
                    fBl[2*p][0] = r[0]; fBl[2*p][1] = r[1];
                    fBl[2*p+1][0] = r[2]; fBl[2*p+1][1] = r[3];
                }
                #pragma unroll
                for (int mt = 0; mt < 4; mt++)
                    #pragma unroll
                    for (int nt = 0; nt < 4; nt++) {
                        float* a4 = acc[mt][ph * 4 + nt];
                        mma_bf16(a4, fAh[mt], fBh[nt]);
                        mma_bf16(a4, fAh[mt], fBl[nt]);
                        mma_bf16(a4, fAl[mt], fBh[nt]);
                    }
            }
        }
    }

    // ---- epilogue ----
    #pragma unroll
    for (int mt = 0; mt < 4; mt++) {
        #pragma unroll
        for (int half = 0; half < 2; half++) {
            const int row = m0 + wm * 64 + mt * 16 + lr + half * 8;
            #pragma unroll
            for (int nt = 0; nt < 8; nt++) {
                const int col = n0 + wn * 64 + nt * 8 + 2 * lc;
                float v0 = acc[mt][nt][2 * half + 0];
                float v1 = acc[mt][nt][2 * half + 1];
                if (GLU) {
                    v0 += bias[col];
                    v1 += bias[col + 1];
                    float gv = v0 / (1.f + __expf(-v1));
                    if (GLUPAIR) {
                        const bool sec = col >= CC;
                        const int j = (sec ? col - CC : col) >> 1;
                        const float* st = sec ? styleS2 : styleS;
                        gv *= st[(row >> 11) * TD + j];
                        bf16 h, l;
                        split_bf16(gv, h, l);
                        const long o = (long)row * TD + j;
                        if (sec) { Ch2[o] = h; Cl2[o] = l; }
                        else     { Ch[o]  = h; Cl[o]  = l; }
                    } else {
                        const int j = col >> 1;
                        if (styleS) gv *= styleS[(row >> 11) * (N >> 1) + j];
                        bf16 h, l;
                        split_bf16(gv, h, l);
                        const long o = (long)row * (N >> 1) + j;
                        Ch[o] = h;
                        Cl[o] = l;
                    }
                } else {
                    if (bias) { v0 += bias[col]; v1 += bias[col + 1]; }
                    const long off = (long)row * N + col;
                    if (resp) {
                        float2 rv = *(const float2*)&resp[off];
                        v0 += rv.x; v1 += rv.y;
                    }
                    if (GELU) { v0 = gelu_f(v0); v1 = gelu_f(v1); }
                    if (FP32O) {
                        *(float2*)&Cf[(long)z * sC + off] = make_float2(v0, v1);
                    }
                    if (SPLIT) {
                        bf16 h0, l0, h1, l1;
                        split_bf16(v0, h0, l0);
                        split_bf16(v1, h1, l1);
                        if (TRANSO) {
                            const long o0 = ((long)(row >> 11) * TD + col) * TT + (row & 2047);
                            const long o1 = o0 + TT;
                            Ch[o0] = h0; Ch[o1] = h1;
                            Cl[o0] = l0; Cl[o1] = l1;
                        } else {
                            const long o = (long)z * sC + off;
                            *(__nv_bfloat162*)(Ch + o) = __nv_bfloat162(h0, h1);
                            *(__nv_bfloat162*)(Cl + o) = __nv_bfloat162(l0, l1);
                        }
                    }
                }
            }
        }
    }
}

// ---------------- host side --------------------------------------------------
static void* symp(const void* s) {
    void* p = nullptr;
    cudaGetSymbolAddress(&p, s);
    return p;
}

#define SMEM128 (3 * (2 * 128 * ASTR * 2 + 2 * 32 * 136 * 2))   // 113664
#define SMEM256 (3 * (2 * 256 * ASTR * 2 + 2 * 32 * 136 * 2))   // 175104

extern "C" void kernel_launch(void* const* d_in, const int* in_sizes, int n_in,
                              void* d_out, int out_size) {
    const float* x     = (const float*)d_in[0];
    const float* w     = (const float*)d_in[1];
    const float* ln1_g = (const float*)d_in[2];
    const float* ln1_b = (const float*)d_in[3];
    const float* ln2_g = (const float*)d_in[4];
    const float* ln2_b = (const float*)d_in[5];
    const float* g1_W  = (const float*)d_in[6];
    const float* g1_b  = (const float*)d_in[7];
    const float* s1_W  = (const float*)d_in[8];
    const float* s1_b  = (const float*)d_in[9];
    const float* m1_W  = (const float*)d_in[10];
    const float* m1_b  = (const float*)d_in[11];
    const float* g2_W  = (const float*)d_in[12];
    const float* g2_b  = (const float*)d_in[13];
    const float* s2_W  = (const float*)d_in[14];
    const float* s2_b  = (const float*)d_in[15];
    const float* m2_W  = (const float*)d_in[16];
    const float* m2_b  = (const float*)d_in[17];
    const float* gs_W  = (const float*)d_in[18];
    const float* gs_b  = (const float*)d_in[19];
    const float* ss_W  = (const float*)d_in[20];
    const float* ss_b  = (const float*)d_in[21];
    const float* ms_W  = (const float*)d_in[22];
    const float* ms_b  = (const float*)d_in[23];
    const float* r1_W  = (const float*)d_in[24];
    const float* r1_b  = (const float*)d_in[25];
    const float* r2_W  = (const float*)d_in[26];
    const float* r2_b  = (const float*)d_in[27];

    float* XLN = (float*)symp(BUF_XLN);
    float* X2  = (float*)symp(BUF_X2);
    float* S1  = (float*)symp(BUF_S1);
    float* S2  = (float*)symp(BUF_S2);
    float* SS  = (float*)symp(BUF_SS);
    float* BI  = (float*)symp(BUF_BI);
    bf16* XLNh = (bf16*)symp(S_XLNh);  bf16* XLNl = (bf16*)symp(S_XLNl);
    bf16* ACTh = (bf16*)symp(S_ACTh);  bf16* ACTl = (bf16*)symp(S_ACTl);
    bf16* A1h  = (bf16*)symp(S_A1h);   bf16* A1l  = (bf16*)symp(S_A1l);
    bf16* A2h  = (bf16*)symp(S_A2h);   bf16* A2l  = (bf16*)symp(S_A2l);
    bf16* H1h  = (bf16*)symp(S_H1h);   bf16* H1l  = (bf16*)symp(S_H1l);
    bf16* H2h  = (bf16*)symp(S_H2h);   bf16* H2l  = (bf16*)symp(S_H2l);
    bf16* MIXh = (bf16*)symp(S_MIXh);  bf16* MIXl = (bf16*)symp(S_MIXl);
    bf16* X3h  = (bf16*)symp(S_X3h);   bf16* X3l  = (bf16*)symp(S_X3l);
    bf16* Wh   = (bf16*)symp(S_Wh);    bf16* Wl   = (bf16*)symp(S_Wl);
    float* OUT = (float*)d_out;

    // dynamic smem opt-in (idempotent)
    cudaFuncSetAttribute(gemm_v5<256,128, true,  true,  false, false, false, false>,
                         cudaFuncAttributeMaxDynamicSharedMemorySize, SMEM256);
    cudaFuncSetAttribute(gemm_v5<256,128, true,  false, false, false, false, false>,
                         cudaFuncAttributeMaxDynamicSharedMemorySize, SMEM256);
    cudaFuncSetAttribute(gemm_v5<256,128, false, false, false, true,  false, false>,
                         cudaFuncAttributeMaxDynamicSharedMemorySize, SMEM256);
    cudaFuncSetAttribute(gemm_v5<256,128, false, false, false, false, false, true>,
                         cudaFuncAttributeMaxDynamicSharedMemorySize, SMEM256);
    cudaFuncSetAttribute(gemm_v5<128,128, false, false, false, true,  true,  false>,
                         cudaFuncAttributeMaxDynamicSharedMemorySize, SMEM128);
    cudaFuncSetAttribute(gemm_v5<128,128, false, false, false, true,  false, false>,
                         cudaFuncAttributeMaxDynamicSharedMemorySize, SMEM128);
    cudaFuncSetAttribute(gemm_v5<128,128, false, false, true,  true,  false, false>,
                         cudaFuncAttributeMaxDynamicSharedMemorySize, SMEM128);

    // 1-2) pack g1|g2 into fused (768, 1536)
    glu_pack_w<<<(long)(CC*CC + 255)/256, 256>>>(g1_W, g1_b, Wh+OFF_G12, Wl+OFF_G12,
                                                 BI+BI_G12, (long)CC*CC, CC, 1536, 0);
    glu_pack_w<<<(long)(CC*CC + 255)/256, 256>>>(g2_W, g2_b, Wh+OFF_G12, Wl+OFF_G12,
                                                 BI+BI_G12, (long)CC*CC, CC, 1536, CC);
    // 3) ln1
    ln_split_kernel<<<ROWS, 256>>>(x, ln1_g, ln1_b, XLN, XLNh, XLNl, CC);
    // 4-5) style S1, S2
    style_s_kernel<<<dim3(TD/32, BB), dim3(32, 32)>>>(w, s1_W, s1_b, S1, 0, TD);
    style_s_kernel<<<dim3(TD/32, BB), dim3(32, 32)>>>(w, s2_W, s2_b, S2, 0, TD);
    // 6) fused GLU1|GLU2 GEMM (profiled by ncu)
    gemm_v5<256,128, true, true, false, false, false, false>
        <<<dim3(1536/128, ROWS/256, 1), 256, SMEM256>>>(
        XLNh, XLNl, Wh+OFF_G12, Wl+OFF_G12, BI+BI_G12, S1, S2, nullptr,
        nullptr, A1h, A1l, A2h, A2l, 1536, CC, CC, 1536, 0, 0, 0, 0);
    // 7) cvt m1
    cvt_split_kernel<<<(TD*TD/4 + 255)/256, 256>>>((const float4*)m1_W, Wh+OFF_M1, Wl+OFF_M1, TD*TD/4);
    // 8) H1(trans) = A1@M1 + b
    gemm_v5<128,128, false, false, false, true, true, false>
        <<<dim3(TD/128, ROWS/128, 1), 128, SMEM128>>>(
        A1h, A1l, Wh+OFF_M1, Wl+OFF_M1, m1_b, nullptr, nullptr, nullptr,
        nullptr, H1h, H1l, nullptr, nullptr, TD, TD, TD, TD, 0, 0, 0, 0);
    // 9) cvt m2
    cvt_split_kernel<<<(TD*TD/4 + 255)/256, 256>>>((const float4*)m2_W, Wh+OFF_M2, Wl+OFF_M2, TD*TD/4);
    // 10) H2 = A2@M2 + b
    gemm_v5<128,128, false, false, false, true, false, false>
        <<<dim3(TD/128, ROWS/128, 1), 128, SMEM128>>>(
        A2h, A2l, Wh+OFF_M2, Wl+OFF_M2, m2_b, nullptr, nullptr, nullptr,
        nullptr, H2h, H2l, nullptr, nullptr, TD, TD, TD, TD, 0, 0, 0, 0);
    // 11) style SS
    style_s_kernel<<<dim3((CD/2)/32, BB), dim3(32, 32)>>>(w, ss_W, ss_b, SS, 1, CD/2);
    // 12) mix[b,d,c] = gelu(sum_t H1[b,d,t] * XLN[b,t,c])   M=TD, N=CC, K=TT
    gemm_v5<128,128, false, false, true, true, false, false>
        <<<dim3(CC/128, TD/128, BB), 128, SMEM128>>>(
        H1h, H1l, XLNh, XLNl, nullptr, nullptr, nullptr, nullptr,
        nullptr, MIXh, MIXl, nullptr, nullptr, CC, TT, TT, CC,
        (long)TD*TT, (long)TT*CC, (long)TD*CC, 0);
    // 13) x2[b,t,c] = sum_d H2[b,t,d] * MIX[b,d,c] + xln    M=TT, N=CC, K=TD
    gemm_v5<256,128, false, false, false, false, false, true>
        <<<dim3(CC/128, TT/256, BB), 256, SMEM256>>>(
        H2h, H2l, MIXh, MIXl, nullptr, nullptr, nullptr, XLN,
        X2, nullptr, nullptr, nullptr, nullptr, CC, TD, TD, CC,
        (long)TT*TD, (long)TD*CC, (long)TT*CC, (long)TT*CC);
    // 14) ln2
    ln_split_kernel<<<ROWS, 256>>>(X2, ln2_g, ln2_b, nullptr, XLNh, XLNl, CC);
    // 15) pack gs
    glu_pack_w<<<(long)(CC*CD + 255)/256, 256>>>(gs_W, gs_b, Wh+OFF_GS, Wl+OFF_GS,
                                                 BI+BI_GS, (long)CC*CD, CD, CD, 0);
    // 16) GLUs GEMM
    gemm_v5<256,128, true, false, false, false, false, false>
        <<<dim3(CD/128, ROWS/256, 1), 256, SMEM256>>>(
        XLNh, XLNl, Wh+OFF_GS, Wl+OFF_GS, BI+BI_GS, SS, nullptr, nullptr,
        nullptr, ACTh, ACTl, nullptr, nullptr, CD, CC, CC, CD, 0, 0, 0, 0);
    // 17) cvt ms
    cvt_split_kernel<<<((CD/2)*CC/4 + 255)/256, 256>>>((const float4*)ms_W, Wh+OFF_MS, Wl+OFF_MS, (CD/2)*CC/4);
    // 18) X3 = ACT@MS + ms_b + X2
    gemm_v5<256,128, false, false, false, true, false, false>
        <<<dim3(CC/128, ROWS/256, 1), 256, SMEM256>>>(
        ACTh, ACTl, Wh+OFF_MS, Wl+OFF_MS, ms_b, nullptr, nullptr, X2,
        nullptr, X3h, X3l, nullptr, nullptr, CC, CD/2, CD/2, CC, 0, 0, 0, 0);
    // 19) pack r1
    glu_pack_w<<<(long)(CC*CC + 255)/256, 256>>>(r1_W, r1_b, Wh+OFF_R1, Wl+OFF_R1,
                                                 BI+BI_R1, (long)CC*CC, CC, CC, 0);
    // 20) head GLU GEMM -> A1
    gemm_v5<256,128, true, false, false, false, false, false>
        <<<dim3(CC/128, ROWS/256, 1), 256, SMEM256>>>(
        X3h, X3l, Wh+OFF_R1, Wl+OFF_R1, BI+BI_R1, nullptr, nullptr, nullptr,
        nullptr, A1h, A1l, nullptr, nullptr, CC, CC, CC, CC, 0, 0, 0, 0);
    // 21) cvt r2
    cvt_split_kernel<<<(TD*CC/4 + 255)/256, 256>>>((const float4*)r2_W, Wh+OFF_R2, Wl+OFF_R2, TD*CC/4);
    // 22) OUT = A1@R2 + b
    gemm_v5<256,128, false, false, false, false, false, true>
        <<<dim3(CC/128, ROWS/256, 1), 256, SMEM256>>>(
        A1h, A1l, Wh+OFF_R2, Wl+OFF_R2, r2_b, nullptr, nullptr, nullptr,
        OUT, nullptr, nullptr, nullptr, nullptr, CC, TD, TD, CC, 0, 0, 0, 0);
}

// round 13
// speedup vs baseline: 1.2092x; 1.2092x over previous
#include <cuda_runtime.h>
#include <cuda_bf16.h>
#include <cstdint>

// Shapes (fixed per problem)
#define BB 8
#define TT 2048
#define CC 768
#define WDIM 512
#define TD 384
#define CD 3072
#define ROWS (BB * TT)          // 16384

// weight pack offsets (elements), layout (K, N) n-contiguous
#define OFF_G12 0               // fused g1|g2, (768, 1536)
#define OFF_M1 1179648
#define OFF_M2 1327104
#define OFF_GS 1474560
#define OFF_MS 3833856
#define OFF_R1 5013504
#define OFF_R2 5603328
#define WTOT   5898240

// bias pack offsets
#define BI_G12 0
#define BI_GS  1536
#define BI_R1  (1536 + CD)

// region sizes for fused weight prep
#define NG  (CC * CC)           // 589824
#define NGS (CC * CD)           // 2359296
#define NM  (TD * TD)           // 147456
#define NMS ((CD/2) * CC)       // 1179648
#define NR2 (TD * CC)           // 294912

typedef __nv_bfloat16 bf16;

// ---------------- scratch (device globals; no allocation allowed) ----------
__device__ float BUF_XLN[ROWS * CC];
__device__ float BUF_X2 [ROWS * CC];
__device__ float BUF_H1F[ROWS * TD];       // fp32 H1 (b,t,d) pre-transpose
__device__ float BUF_S1 [BB * TD];
__device__ float BUF_S2 [BB * TD];
__device__ float BUF_SS [BB * (CD/2)];
__device__ float BUF_BI [1536 + CD + CC];

__device__ bf16 S_XLNh[ROWS * CC],      S_XLNl[ROWS * CC];
__device__ bf16 S_ACTh[ROWS * (CD/2)],  S_ACTl[ROWS * (CD/2)];
__device__ bf16 S_A1h [ROWS * TD],      S_A1l [ROWS * TD];
__device__ bf16 S_A2h [ROWS * TD],      S_A2l [ROWS * TD];
__device__ bf16 S_H1h [BB * TD * TT],   S_H1l [BB * TD * TT];   // (b,d,t)
__device__ bf16 S_H2h [ROWS * TD],      S_H2l [ROWS * TD];      // (b,t,d)
__device__ bf16 S_MIXh[BB * TD * CC],   S_MIXl[BB * TD * CC];   // (b,d,c)
__device__ bf16 S_X3h [ROWS * CC],      S_X3l [ROWS * CC];
__device__ bf16 S_Wh  [WTOT],           S_Wl  [WTOT];

// ---------------- helpers ---------------------------------------------------
__device__ __forceinline__ float gelu_f(float v) {
    return 0.5f * v * (1.0f + erff(v * 0.70710678118654752f));
}
__device__ __forceinline__ void split_bf16(float v, bf16& h, bf16& l) {
    h = __float2bfloat16_rn(v);
    l = __float2bfloat16_rn(v - __bfloat162float(h));
}
__device__ __forceinline__ void cp16(void* smem, const void* gmem) {
    uint32_t s = (uint32_t)__cvta_generic_to_shared(smem);
    asm volatile("cp.async.cg.shared.global [%0], [%1], 16;" :: "r"(s), "l"(gmem));
}
__device__ __forceinline__ void cp_commit() { asm volatile("cp.async.commit_group;"); }

__device__ __forceinline__ void ldsm4(uint32_t* r, const void* p) {
    uint32_t a = (uint32_t)__cvta_generic_to_shared(p);
    asm volatile("ldmatrix.sync.aligned.m8n8.x4.shared.b16 {%0,%1,%2,%3}, [%4];"
                 : "=r"(r[0]), "=r"(r[1]), "=r"(r[2]), "=r"(r[3]) : "r"(a));
}
__device__ __forceinline__ void ldsm4t(uint32_t* r, const void* p) {
    uint32_t a = (uint32_t)__cvta_generic_to_shared(p);
    asm volatile("ldmatrix.sync.aligned.m8n8.x4.trans.shared.b16 {%0,%1,%2,%3}, [%4];"
                 : "=r"(r[0]), "=r"(r[1]), "=r"(r[2]), "=r"(r[3]) : "r"(a));
}
__device__ __forceinline__ void mma_bf16(float* d, const uint32_t* a, const uint32_t* b) {
    asm volatile(
        "mma.sync.aligned.m16n8k16.row.col.f32.bf16.bf16.f32 "
        "{%0,%1,%2,%3}, {%4,%5,%6,%7}, {%8,%9}, {%0,%1,%2,%3};"
        : "+f"(d[0]), "+f"(d[1]), "+f"(d[2]), "+f"(d[3])
        : "r"(a[0]), "r"(a[1]), "r"(a[2]), "r"(a[3]), "r"(b[0]), "r"(b[1]));
}

// ---------------- LayerNorm (+ bf16 split output) ----------------------------
__global__ void ln_split_kernel(const float* __restrict__ x,
                                const float* __restrict__ g,
                                const float* __restrict__ b,
                                float* __restrict__ yf,
                                bf16* __restrict__ yh,
                                bf16* __restrict__ yl, int C) {
    __shared__ float red[2][8];
    long row = blockIdx.x;
    const float* xr = x + row * C;
    float s = 0.f, s2 = 0.f;
    for (int c = threadIdx.x; c < C; c += blockDim.x) {
        float v = xr[c];
        s += v; s2 += v * v;
    }
    #pragma unroll
    for (int o = 16; o; o >>= 1) {
        s  += __shfl_xor_sync(0xFFFFFFFFu, s,  o);
        s2 += __shfl_xor_sync(0xFFFFFFFFu, s2, o);
    }
    int w = threadIdx.x >> 5, l = threadIdx.x & 31;
    if (l == 0) { red[0][w] = s; red[1][w] = s2; }
    __syncthreads();
    if (threadIdx.x < 32) {
        s  = (l < 8) ? red[0][l] : 0.f;
        s2 = (l < 8) ? red[1][l] : 0.f;
        #pragma unroll
        for (int o = 4; o; o >>= 1) {
            s  += __shfl_xor_sync(0xFFFFFFFFu, s,  o);
            s2 += __shfl_xor_sync(0xFFFFFFFFu, s2, o);
        }
        if (l == 0) { red[0][0] = s; red[1][0] = s2; }
    }
    __syncthreads();
    float mu  = red[0][0] / C;
    float var = red[1][0] / C - mu * mu;
    float inv = rsqrtf(var + 1e-6f);
    for (int c = threadIdx.x; c < C; c += blockDim.x) {
        float v = (xr[c] - mu) * inv * g[c] + b[c];
        if (yf) yf[row * C + c] = v;
        bf16 h, lo;
        split_bf16(v, h, lo);
        yh[row * C + c] = h;
        yl[row * C + c] = lo;
    }
}

// ---------------- fused weight prep (all 8 matrices, one launch) -------------
__device__ __forceinline__ void prep_pack(const float* W, const float* b,
                                          bf16* oh, bf16* ol, float* biasI,
                                          long i, int H, int ld, int coloff) {
    long k = i / H;
    int  n = (int)(i - k * H);
    int  src = (n & 1) ? (n >> 1) + (H >> 1) : (n >> 1);
    bf16 h, l;
    split_bf16(W[k * H + src], h, l);
    const long o = k * ld + coloff + n;
    oh[o] = h;
    ol[o] = l;
    if (k == 0) biasI[coloff + n] = b[src];
}
__device__ __forceinline__ void prep_cvt(const float* W, bf16* oh, bf16* ol, long i) {
    bf16 h, l;
    split_bf16(W[i], h, l);
    oh[i] = h;
    ol[i] = l;
}

__global__ void weight_prep_kernel(
    const float* __restrict__ g1W, const float* __restrict__ g1b,
    const float* __restrict__ g2W, const float* __restrict__ g2b,
    const float* __restrict__ gsW, const float* __restrict__ gsb,
    const float* __restrict__ r1W, const float* __restrict__ r1b,
    const float* __restrict__ m1W, const float* __restrict__ m2W,
    const float* __restrict__ msW, const float* __restrict__ r2W,
    bf16* __restrict__ Wh, bf16* __restrict__ Wl, float* __restrict__ BI)
{
    long i = (long)blockIdx.x * blockDim.x + threadIdx.x;
    if (i < NG) { prep_pack(g1W, g1b, Wh+OFF_G12, Wl+OFF_G12, BI+BI_G12, i, CC, 1536, 0); return; }
    i -= NG;
    if (i < NG) { prep_pack(g2W, g2b, Wh+OFF_G12, Wl+OFF_G12, BI+BI_G12, i, CC, 1536, CC); return; }
    i -= NG;
    if (i < NGS){ prep_pack(gsW, gsb, Wh+OFF_GS,  Wl+OFF_GS,  BI+BI_GS,  i, CD, CD, 0); return; }
    i -= NGS;
    if (i < NG) { prep_pack(r1W, r1b, Wh+OFF_R1,  Wl+OFF_R1,  BI+BI_R1,  i, CC, CC, 0); return; }
    i -= NG;
    if (i < NM) { prep_cvt(m1W, Wh+OFF_M1, Wl+OFF_M1, i); return; }
    i -= NM;
    if (i < NM) { prep_cvt(m2W, Wh+OFF_M2, Wl+OFF_M2, i); return; }
    i -= NM;
    if (i < NMS){ prep_cvt(msW, Wh+OFF_MS, Wl+OFF_MS, i); return; }
    i -= NMS;
    if (i < NR2){ prep_cvt(r2W, Wh+OFF_R2, Wl+OFF_R2, i); return; }
}

// ---------------- tiled transpose + split: (b,t,d) fp32 -> (b,d,t) hi/lo -----
__global__ void trans_split_kernel(const float* __restrict__ in,
                                   bf16* __restrict__ oh,
                                   bf16* __restrict__ ol, int R, int C) {
    __shared__ float tile[32][33];
    long zo = (long)blockIdx.z * R * C;
    in += zo; oh += zo; ol += zo;
    int r0 = blockIdx.y * 32, c0 = blockIdx.x * 32;
    for (int i = threadIdx.y; i < 32; i += 8)
        tile[i][threadIdx.x] = in[(long)(r0 + i) * C + c0 + threadIdx.x];
    __syncthreads();
    for (int i = threadIdx.y; i < 32; i += 8) {
        float v = tile[threadIdx.x][i];
        bf16 h, l;
        split_bf16(v, h, l);
        long o = (long)(c0 + i) * R + r0 + threadIdx.x;
        oh[o] = h;
        ol[o] = l;
    }
}

// ---------------- style-projection: block (32,32), k-split 16 ----------------
__global__ void style_s_kernel(const float* __restrict__ w,
                               const float* __restrict__ sW,
                               const float* __restrict__ sb,
                               float* __restrict__ out, int sel, int N) {
    __shared__ float red[32][33];
    const int b = blockIdx.y;
    const int n = blockIdx.x * 32 + threadIdx.x;
    const int ky = threadIdx.y;
    const float* wr = w + b * (2 * WDIM) + sel * WDIM;
    float acc = 0.f;
    #pragma unroll
    for (int k = ky * 16; k < ky * 16 + 16; k++)
        acc += wr[k] * sW[(long)k * N + n];
    red[ky][threadIdx.x] = acc;
    __syncthreads();
    if (ky == 0) {
        float s = sb[n];
        #pragma unroll
        for (int i = 0; i < 32; i++) s += red[i][threadIdx.x];
        out[b * N + n] = s;
    }
}

// ---------------- bf16x3 mma.sync GEMM (round-8 proven config) ---------------
// C(M,N) = (Ah+Al)(M,K) @ (Bh+Bl)(K,N)  (lo*lo dropped)
// A k-contig (lda), B n-contig (ldb). CTA 128x128x32, 128 thr, 4 warps 2x2,
// warp tile 64x64. 3-stage cp.async pipeline.
#define ASTR 40
#define BSTR 136
#define A_BYTES (128 * ASTR * 2)
#define B_BYTES (32 * BSTR * 2)
#define STAGEB  (2 * A_BYTES + 2 * B_BYTES)   // 37888
#define SMEMB   (3 * STAGEB)                  // 113664

template <bool GLU, bool GLUPAIR, bool GELU, bool SPLIT, bool FP32O>
__global__ __launch_bounds__(128) void gemm_v6(
    const bf16* __restrict__ Ah, const bf16* __restrict__ Al,
    const bf16* __restrict__ Bh, const bf16* __restrict__ Bl,
    const float* __restrict__ bias,
    const float* __restrict__ styleS, const float* __restrict__ styleS2,
    const float* __restrict__ res,
    float* __restrict__ Cf, bf16* __restrict__ Ch, bf16* __restrict__ Cl,
    bf16* __restrict__ Ch2, bf16* __restrict__ Cl2,
    int N, int K, int lda, int ldb,
    long sA, long sB, long sC, long sRes)
{
    extern __shared__ char smem[];

    const int z = blockIdx.z;
    const bf16* Agh = Ah + (long)z * sA;
    const bf16* Agl = Al + (long)z * sA;
    const bf16* Bgh = Bh + (long)z * sB;
    const bf16* Bgl = Bl + (long)z * sB;
    const float* resp = res ? res + (long)z * sRes : nullptr;

    const int m0 = blockIdx.y * 128, n0 = blockIdx.x * 128;
    const int tid = threadIdx.x;
    const int lane = tid & 31, wid = tid >> 5;
    const int wm = wid >> 1, wn = wid & 1;
    const int lr = lane >> 2, lc = lane & 3;

    const int aoffL = (lane & 15) * ASTR + ((lane >> 4) << 3);
    const int boffC = ((lane >> 4) << 3);

    float acc[4][8][4];
    #pragma unroll
    for (int i = 0; i < 4; i++)
        #pragma unroll
        for (int j = 0; j < 8; j++) {
            acc[i][j][0] = 0.f; acc[i][j][1] = 0.f;
            acc[i][j][2] = 0.f; acc[i][j][3] = 0.f;
        }

    auto loadStage = [&](int st, int k0) {
        char* base = smem + st * STAGEB;
        bf16* ah = (bf16*)(base);
        bf16* al = (bf16*)(base + A_BYTES);
        bf16* bh = (bf16*)(base + 2 * A_BYTES);
        bf16* bl = (bf16*)(base + 2 * A_BYTES + B_BYTES);
        #pragma unroll
        for (int i = tid; i < 512; i += 128) {
            const int r = i >> 2, c = i & 3;
            const long go = (long)(m0 + r) * lda + k0 + c * 8;
            const int so = r * ASTR + c * 8;
            cp16(ah + so, Agh + go);
            cp16(al + so, Agl + go);
        }
        #pragma unroll
        for (int i = tid; i < 512; i += 128) {
            const int r = i >> 4, c = i & 15;
            const long go = (long)(k0 + r) * ldb + n0 + c * 8;
            const int so = r * BSTR + c * 8;
            cp16(bh + so, Bgh + go);
            cp16(bl + so, Bgl + go);
        }
        cp_commit();
    };

    const int NST = K >> 5;
    loadStage(0, 0);
    if (NST > 1) loadStage(1, 32);

    for (int it = 0; it < NST; it++) {
        const int st = it % 3;
        if (it + 2 <= NST) asm volatile("cp.async.wait_group 1;" ::: "memory");
        else               asm volatile("cp.async.wait_group 0;" ::: "memory");
        __syncthreads();

        char* base = smem + st * STAGEB;
        const bf16* ah = (const bf16*)(base);
        const bf16* al = (const bf16*)(base + A_BYTES);
        const bf16* bh = (const bf16*)(base + 2 * A_BYTES);
        const bf16* bl = (const bf16*)(base + 2 * A_BYTES + B_BYTES);

        #pragma unroll
        for (int ks = 0; ks < 2; ks++) {
            uint32_t fAh[4][4], fAl[4][4];
            const int aoff = aoffL + ks * 16;
            #pragma unroll
            for (int mt = 0; mt < 4; mt++) {
                const int mb = (wm * 64 + mt * 16) * ASTR + aoff;
                ldsm4(fAh[mt], ah + mb);
                ldsm4(fAl[mt], al + mb);
            }
            const int brow = (ks * 16 + (lane & 15)) * BSTR + boffC;
            #pragma unroll
            for (int ph = 0; ph < 2; ph++) {
                uint32_t fBh[4][2], fBl[4][2];
                #pragma unroll
                for (int p = 0; p < 2; p++) {
                    const int nb = brow + wn * 64 + ph * 32 + p * 16;
                    uint32_t r[4];
                    ldsm4t(r, bh + nb);
                    fBh[2*p][0] = r[0]; fBh[2*p][1] = r[1];
                    fBh[2*p+1][0] = r[2]; fBh[2*p+1][1] = r[3];
                    ldsm4t(r, bl + nb);
                    fBl[2*p][0] = r[0]; fBl[2*p][1] = r[1];
                    fBl[2*p+1][0] = r[2]; fBl[2*p+1][1] = r[3];
                }
                #pragma unroll
                for (int mt = 0; mt < 4; mt++)
                    #pragma unroll
                    for (int nt = 0; nt < 4; nt++) {
                        float* a4 = acc[mt][ph * 4 + nt];
                        mma_bf16(a4, fAh[mt], fBh[nt]);
                        mma_bf16(a4, fAh[mt], fBl[nt]);
                        mma_bf16(a4, fAl[mt], fBh[nt]);
                    }
            }
        }
        if (it + 2 < NST) loadStage((it + 2) % 3, (it + 2) << 5);
    }

    // ---- epilogue ----
    #pragma unroll
    for (int mt = 0; mt < 4; mt++) {
        #pragma unroll
        for (int half = 0; half < 2; half++) {
            const int row = m0 + wm * 64 + mt * 16 + lr + half * 8;
            #pragma unroll
            for (int nt = 0; nt < 8; nt++) {
                const int col = n0 + wn * 64 + nt * 8 + 2 * lc;
                float v0 = acc[mt][nt][2 * half + 0];
                float v1 = acc[mt][nt][2 * half + 1];
                if (GLU) {
                    v0 += bias[col];
                    v1 += bias[col + 1];
                    float gv = v0 / (1.f + __expf(-v1));
                    if (GLUPAIR) {
                        const bool sec = col >= CC;
                        const int j = (sec ? col - CC : col) >> 1;
                        const float* st = sec ? styleS2 : styleS;
                        gv *= st[(row >> 11) * TD + j];
                        bf16 h, l;
                        split_bf16(gv, h, l);
                        const long o = (long)row * TD + j;
                        if (sec) { Ch2[o] = h; Cl2[o] = l; }
                        else     { Ch[o]  = h; Cl[o]  = l; }
                    } else {
                        const int j = col >> 1;
                        if (styleS) gv *= styleS[(row >> 11) * (N >> 1) + j];
                        bf16 h, l;
                        split_bf16(gv, h, l);
                        const long o = (long)row * (N >> 1) + j;
                        Ch[o] = h;
                        Cl[o] = l;
                    }
                } else {
                    if (bias) { v0 += bias[col]; v1 += bias[col + 1]; }
                    const long off = (long)row * N + col;
                    if (resp) {
                        float2 rv = *(const float2*)&resp[off];
                        v0 += rv.x; v1 += rv.y;
                    }
                    if (GELU) { v0 = gelu_f(v0); v1 = gelu_f(v1); }
                    if (FP32O) {
                        *(float2*)&Cf[(long)z * sC + off] = make_float2(v0, v1);
                    }
                    if (SPLIT) {
                        bf16 h0, l0, h1, l1;
                        split_bf16(v0, h0, l0);
                        split_bf16(v1, h1, l1);
                        const long o = (long)z * sC + off;
                        *(__nv_bfloat162*)(Ch + o) = __nv_bfloat162(h0, h1);
                        *(__nv_bfloat162*)(Cl + o) = __nv_bfloat162(l0, l1);
                    }
                }
            }
        }
    }
}

// ---------------- host side --------------------------------------------------
static void* symp(const void* s) {
    void* p = nullptr;
    cudaGetSymbolAddress(&p, s);
    return p;
}

extern "C" void kernel_launch(void* const* d_in, const int* in_sizes, int n_in,
                              void* d_out, int out_size) {
    const float* x     = (const float*)d_in[0];
    const float* w     = (const float*)d_in[1];
    const float* ln1_g = (const float*)d_in[2];
    const float* ln1_b = (const float*)d_in[3];
    const float* ln2_g = (const float*)d_in[4];
    const float* ln2_b = (const float*)d_in[5];
    const float* g1_W  = (const float*)d_in[6];
    const float* g1_b  = (const float*)d_in[7];
    const float* s1_W  = (const float*)d_in[8];
    const float* s1_b  = (const float*)d_in[9];
    const float* m1_W  = (const float*)d_in[10];
    const float* m1_b  = (const float*)d_in[11];
    const float* g2_W  = (const float*)d_in[12];
    const float* g2_b  = (const float*)d_in[13];
    const float* s2_W  = (const float*)d_in[14];
    const float* s2_b  = (const float*)d_in[15];
    const float* m2_W  = (const float*)d_in[16];
    const float* m2_b  = (const float*)d_in[17];
    const float* gs_W  = (const float*)d_in[18];
    const float* gs_b  = (const float*)d_in[19];
    const float* ss_W  = (const float*)d_in[20];
    const float* ss_b  = (const float*)d_in[21];
    const float* ms_W  = (const float*)d_in[22];
    const float* ms_b  = (const float*)d_in[23];
    const float* r1_W  = (const float*)d_in[24];
    const float* r1_b  = (const float*)d_in[25];
    const float* r2_W  = (const float*)d_in[26];
    const float* r2_b  = (const float*)d_in[27];

    float* XLN = (float*)symp(BUF_XLN);
    float* X2  = (float*)symp(BUF_X2);
    float* H1F = (float*)symp(BUF_H1F);
    float* S1  = (float*)symp(BUF_S1);
    float* S2  = (float*)symp(BUF_S2);
    float* SS  = (float*)symp(BUF_SS);
    float* BI  = (float*)symp(BUF_BI);
    bf16* XLNh = (bf16*)symp(S_XLNh);  bf16* XLNl = (bf16*)symp(S_XLNl);
    bf16* ACTh = (bf16*)symp(S_ACTh);  bf16* ACTl = (bf16*)symp(S_ACTl);
    bf16* A1h  = (bf16*)symp(S_A1h);   bf16* A1l  = (bf16*)symp(S_A1l);
    bf16* A2h  = (bf16*)symp(S_A2h);   bf16* A2l  = (bf16*)symp(S_A2l);
    bf16* H1h  = (bf16*)symp(S_H1h);   bf16* H1l  = (bf16*)symp(S_H1l);
    bf16* H2h  = (bf16*)symp(S_H2h);   bf16* H2l  = (bf16*)symp(S_H2l);
    bf16* MIXh = (bf16*)symp(S_MIXh);  bf16* MIXl = (bf16*)symp(S_MIXl);
    bf16* X3h  = (bf16*)symp(S_X3h);   bf16* X3l  = (bf16*)symp(S_X3l);
    bf16* Wh   = (bf16*)symp(S_Wh);    bf16* Wl   = (bf16*)symp(S_Wl);
    float* OUT = (float*)d_out;

    // dynamic smem opt-in (idempotent)
    cudaFuncSetAttribute(gemm_v6<true,  true,  false, false, false>,
                         cudaFuncAttributeMaxDynamicSharedMemorySize, SMEMB);
    cudaFuncSetAttribute(gemm_v6<true,  false, false, false, false>,
                         cudaFuncAttributeMaxDynamicSharedMemorySize, SMEMB);
    cudaFuncSetAttribute(gemm_v6<false, false, false, true,  false>,
                         cudaFuncAttributeMaxDynamicSharedMemorySize, SMEMB);
    cudaFuncSetAttribute(gemm_v6<false, false, true,  true,  false>,
                         cudaFuncAttributeMaxDynamicSharedMemorySize, SMEMB);
    cudaFuncSetAttribute(gemm_v6<false, false, false, false, true>,
                         cudaFuncAttributeMaxDynamicSharedMemorySize, SMEMB);

    // 1) fused weight prep (single launch, all 8 matrices)
    weight_prep_kernel<<<WTOT / 256, 256>>>(
        g1_W, g1_b, g2_W, g2_b, gs_W, gs_b, r1_W, r1_b,
        m1_W, m2_W, ms_W, r2_W, Wh, Wl, BI);
    // 2) ln1
    ln_split_kernel<<<ROWS, 256>>>(x, ln1_g, ln1_b, XLN, XLNh, XLNl, CC);
    // 3-5) style S1, S2, SS
    style_s_kernel<<<dim3(TD/32, BB), dim3(32, 32)>>>(w, s1_W, s1_b, S1, 0, TD);
    style_s_kernel<<<dim3(TD/32, BB), dim3(32, 32)>>>(w, s2_W, s2_b, S2, 0, TD);
    style_s_kernel<<<dim3((CD/2)/32, BB), dim3(32, 32)>>>(w, ss_W, ss_b, SS, 1, CD/2);
    // 6) fused GLU1|GLU2 GEMM -> A1, A2   (profiled by ncu -s 5)
    gemm_v6<true, true, false, false, false>
        <<<dim3(1536/128, ROWS/128, 1), 128, SMEMB>>>(
        XLNh, XLNl, Wh+OFF_G12, Wl+OFF_G12, BI+BI_G12, S1, S2, nullptr,
        nullptr, A1h, A1l, A2h, A2l, 1536, CC, CC, 1536, 0, 0, 0, 0);
    // 7) H1F (b,t,d) fp32 = A1@M1 + b
    gemm_v6<false, false, false, false, true>
        <<<dim3(TD/128, ROWS/128, 1), 128, SMEMB>>>(
        A1h, A1l, Wh+OFF_M1, Wl+OFF_M1, m1_b, nullptr, nullptr, nullptr,
        H1F, nullptr, nullptr, nullptr, nullptr, TD, TD, TD, TD, 0, 0, 0, 0);
    // 8) H1 (b,d,t) hi/lo via coalesced transpose+split
    trans_split_kernel<<<dim3(TD/32, TT/32, BB), dim3(32, 8)>>>(H1F, H1h, H1l, TT, TD);
    // 9) H2 = A2@M2 + b (split, t-major)
    gemm_v6<false, false, false, true, false>
        <<<dim3(TD/128, ROWS/128, 1), 128, SMEMB>>>(
        A2h, A2l, Wh+OFF_M2, Wl+OFF_M2, m2_b, nullptr, nullptr, nullptr,
        nullptr, H2h, H2l, nullptr, nullptr, TD, TD, TD, TD, 0, 0, 0, 0);
    // 10) mix[b,d,c] = gelu(sum_t H1[b,d,t] * XLN[b,t,c])   M=TD, N=CC, K=TT
    gemm_v6<false, false, true, true, false>
        <<<dim3(CC/128, TD/128, BB), 128, SMEMB>>>(
        H1h, H1l, XLNh, XLNl, nullptr, nullptr, nullptr, nullptr,
        nullptr, MIXh, MIXl, nullptr, nullptr, CC, TT, TT, CC,
        (long)TD*TT, (long)TT*CC, (long)TD*CC, 0);
    // 11) x2[b,t,c] = sum_d H2[b,t,d] * MIX[b,d,c] + xln    M=TT, N=CC, K=TD
    gemm_v6<false, false, false, false, true>
        <<<dim3(CC/128, TT/128, BB), 128, SMEMB>>>(
        H2h, H2l, MIXh, MIXl, nullptr, nullptr, nullptr, XLN,
        X2, nullptr, nullptr, nullptr, nullptr, CC, TD, TD, CC,
        (long)TT*TD, (long)TD*CC, (long)TT*CC, (long)TT*CC);
    // 12) ln2
    ln_split_kernel<<<ROWS, 256>>>(X2, ln2_g, ln2_b, nullptr, XLNh, XLNl, CC);
    // 13) GLUs GEMM -> ACT
    gemm_v6<true, false, false, false, false>
        <<<dim3(CD/128, ROWS/128, 1), 128, SMEMB>>>(
        XLNh, XLNl, Wh+OFF_GS, Wl+OFF_GS, BI+BI_GS, SS, nullptr, nullptr,
        nullptr, ACTh, ACTl, nullptr, nullptr, CD, CC, CC, CD, 0, 0, 0, 0);
    // 14) X3 = ACT@MS + ms_b + X2 (split)
    gemm_v6<false, false, false, true, false>
        <<<dim3(CC/128, ROWS/128, 1), 128, SMEMB>>>(
        ACTh, ACTl, Wh+OFF_MS, Wl+OFF_MS, ms_b, nullptr, nullptr, X2,
        nullptr, X3h, X3l, nullptr, nullptr, CC, CD/2, CD/2, CC, 0, 0, 0, 0);
    // 15) head GLU GEMM -> A1
    gemm_v6<true, false, false, false, false>
        <<<dim3(CC/128, ROWS/128, 1), 128, SMEMB>>>(
        X3h, X3l, Wh+OFF_R1, Wl+OFF_R1, BI+BI_R1, nullptr, nullptr, nullptr,
        nullptr, A1h, A1l, nullptr, nullptr, CC, CC, CC, CC, 0, 0, 0, 0);
    // 16) OUT = A1@R2 + b
    gemm_v6<false, false, false, false, true>
        <<<dim3(CC/128, ROWS/128, 1), 128, SMEMB>>>(
        A1h, A1l, Wh+OFF_R2, Wl+OFF_R2, r2_b, nullptr, nullptr, nullptr,
        OUT, nullptr, nullptr, nullptr, nullptr, CC, TD, TD, CC, 0, 0, 0, 0);
}

// round 14
// speedup vs baseline: 1.2329x; 1.0196x over previous
#include <cuda_runtime.h>
#include <cuda_bf16.h>
#include <cstdint>

// Shapes (fixed per problem)
#define BB 8
#define TT 2048
#define CC 768
#define WDIM 512
#define TD 384
#define CD 3072
#define ROWS (BB * TT)          // 16384

// weight pack offsets (elements), layout (K, N) n-contiguous
#define OFF_G12 0               // fused g1|g2, (768, 1536)
#define OFF_M1 1179648
#define OFF_M2 1327104
#define OFF_GS 1474560
#define OFF_MS 3833856
#define OFF_R1 5013504
#define OFF_R2 5603328
#define WTOT   5898240

// bias pack offsets
#define BI_G12 0
#define BI_GS  1536
#define BI_R1  (1536 + CD)

// region sizes for fused weight prep
#define NG  (CC * CC)           // 589824
#define NGS (CC * CD)           // 2359296
#define NM  (TD * TD)           // 147456
#define NMS ((CD/2) * CC)       // 1179648
#define NR2 (TD * CC)           // 294912

// prep_all grid regions (blocks of 256 threads)
#define NB_W  (WTOT / 256)          // 23040
#define NB_LN ROWS                  // 16384
#define NB_S1 ((TD / 32) * BB)      // 96
#define NB_SS (((CD/2) / 32) * BB)  // 384
#define NB_ALL (NB_W + NB_LN + 2 * NB_S1 + NB_SS)   // 40000

typedef __nv_bfloat16 bf16;

// ---------------- scratch (device globals; no allocation allowed) ----------
__device__ float BUF_XLN[ROWS * CC];
__device__ float BUF_X2 [ROWS * CC];
__device__ float BUF_H1F[ROWS * TD];       // fp32 H1 (b,t,d) pre-transpose
__device__ float BUF_S1 [BB * TD];
__device__ float BUF_S2 [BB * TD];
__device__ float BUF_SS [BB * (CD/2)];
__device__ float BUF_BI [1536 + CD + CC];

__device__ bf16 S_XLNh[ROWS * CC],      S_XLNl[ROWS * CC];
__device__ bf16 S_ACTh[ROWS * (CD/2)],  S_ACTl[ROWS * (CD/2)];
__device__ bf16 S_A1h [ROWS * TD],      S_A1l [ROWS * TD];
__device__ bf16 S_A2h [ROWS * TD],      S_A2l [ROWS * TD];
__device__ bf16 S_H1h [BB * TD * TT],   S_H1l [BB * TD * TT];   // (b,d,t)
__device__ bf16 S_H2h [ROWS * TD],      S_H2l [ROWS * TD];      // (b,t,d)
__device__ bf16 S_MIXh[BB * TD * CC],   S_MIXl[BB * TD * CC];   // (b,d,c)
__device__ bf16 S_X3h [ROWS * CC],      S_X3l [ROWS * CC];
__device__ bf16 S_Wh  [WTOT],           S_Wl  [WTOT];

// ---------------- helpers ---------------------------------------------------
__device__ __forceinline__ float gelu_f(float v) {
    return 0.5f * v * (1.0f + erff(v * 0.70710678118654752f));
}
__device__ __forceinline__ void split_bf16(float v, bf16& h, bf16& l) {
    h = __float2bfloat16_rn(v);
    l = __float2bfloat16_rn(v - __bfloat162float(h));
}
__device__ __forceinline__ void cp16(void* smem, const void* gmem) {
    uint32_t s = (uint32_t)__cvta_generic_to_shared(smem);
    asm volatile("cp.async.cg.shared.global [%0], [%1], 16;" :: "r"(s), "l"(gmem));
}
__device__ __forceinline__ void cp_commit() { asm volatile("cp.async.commit_group;"); }

__device__ __forceinline__ void ldsm4(uint32_t* r, const void* p) {
    uint32_t a = (uint32_t)__cvta_generic_to_shared(p);
    asm volatile("ldmatrix.sync.aligned.m8n8.x4.shared.b16 {%0,%1,%2,%3}, [%4];"
                 : "=r"(r[0]), "=r"(r[1]), "=r"(r[2]), "=r"(r[3]) : "r"(a));
}
__device__ __forceinline__ void ldsm4t(uint32_t* r, const void* p) {
    uint32_t a = (uint32_t)__cvta_generic_to_shared(p);
    asm volatile("ldmatrix.sync.aligned.m8n8.x4.trans.shared.b16 {%0,%1,%2,%3}, [%4];"
                 : "=r"(r[0]), "=r"(r[1]), "=r"(r[2]), "=r"(r[3]) : "r"(a));
}
__device__ __forceinline__ void mma_bf16(float* d, const uint32_t* a, const uint32_t* b) {
    asm volatile(
        "mma.sync.aligned.m16n8k16.row.col.f32.bf16.bf16.f32 "
        "{%0,%1,%2,%3}, {%4,%5,%6,%7}, {%8,%9}, {%0,%1,%2,%3};"
        : "+f"(d[0]), "+f"(d[1]), "+f"(d[2]), "+f"(d[3])
        : "r"(a[0]), "r"(a[1]), "r"(a[2]), "r"(a[3]), "r"(b[0]), "r"(b[1]));
}

// ---------------- LayerNorm body (shared by prep_all and ln2) ---------------
__device__ __forceinline__ void ln_row_body(
    const float* __restrict__ x, const float* __restrict__ g,
    const float* __restrict__ b, float* __restrict__ yf,
    bf16* __restrict__ yh, bf16* __restrict__ yl,
    long row, float (*red)[33])
{
    const float* xr = x + row * CC;
    float s = 0.f, s2 = 0.f;
    for (int c = threadIdx.x; c < CC; c += 256) {
        float v = xr[c];
        s += v; s2 += v * v;
    }
    #pragma unroll
    for (int o = 16; o; o >>= 1) {
        s  += __shfl_xor_sync(0xFFFFFFFFu, s,  o);
        s2 += __shfl_xor_sync(0xFFFFFFFFu, s2, o);
    }
    int w = threadIdx.x >> 5, l = threadIdx.x & 31;
    if (l == 0) { red[0][w] = s; red[1][w] = s2; }
    __syncthreads();
    if (threadIdx.x < 32) {
        s  = (l < 8) ? red[0][l] : 0.f;
        s2 = (l < 8) ? red[1][l] : 0.f;
        #pragma unroll
        for (int o = 4; o; o >>= 1) {
            s  += __shfl_xor_sync(0xFFFFFFFFu, s,  o);
            s2 += __shfl_xor_sync(0xFFFFFFFFu, s2, o);
        }
        if (l == 0) { red[0][0] = s; red[1][0] = s2; }
    }
    __syncthreads();
    float mu  = red[0][0] / CC;
    float var = red[1][0] / CC - mu * mu;
    float inv = rsqrtf(var + 1e-6f);
    for (int c = threadIdx.x; c < CC; c += 256) {
        float v = (xr[c] - mu) * inv * g[c] + b[c];
        if (yf) yf[row * CC + c] = v;
        bf16 h, lo;
        split_bf16(v, h, lo);
        yh[row * CC + c] = h;
        yl[row * CC + c] = lo;
    }
}

__global__ void ln_split_kernel(const float* __restrict__ x,
                                const float* __restrict__ g,
                                const float* __restrict__ b,
                                float* __restrict__ yf,
                                bf16* __restrict__ yh,
                                bf16* __restrict__ yl) {
    __shared__ float red[8][33];
    ln_row_body(x, g, b, yf, yh, yl, blockIdx.x, red);
}

// ---------------- weight prep pieces -----------------------------------------
__device__ __forceinline__ void prep_pack(const float* W, const float* b,
                                          bf16* oh, bf16* ol, float* biasI,
                                          long i, int H, int ld, int coloff) {
    long k = i / H;
    int  n = (int)(i - k * H);
    int  src = (n & 1) ? (n >> 1) + (H >> 1) : (n >> 1);
    bf16 h, l;
    split_bf16(W[k * H + src], h, l);
    const long o = k * ld + coloff + n;
    oh[o] = h;
    ol[o] = l;
    if (k == 0) biasI[coloff + n] = b[src];
}
__device__ __forceinline__ void prep_cvt(const float* W, bf16* oh, bf16* ol, long i) {
    bf16 h, l;
    split_bf16(W[i], h, l);
    oh[i] = h;
    ol[i] = l;
}

// ---------------- style body: 32 cols x 8 k-slices of 64 ---------------------
__device__ __forceinline__ void style_body(
    const float* __restrict__ w, const float* __restrict__ sW,
    const float* __restrict__ sb, float* __restrict__ out,
    int sel, int N, int rblk, float (*red)[33])
{
    const int nb = N / 32;
    const int bidx = rblk / nb;
    const int nblk = rblk - bidx * nb;
    const int tx = threadIdx.x & 31, ky = threadIdx.x >> 5;
    const int n = nblk * 32 + tx;
    const float* wr = w + bidx * (2 * WDIM) + sel * WDIM;
    float acc = 0.f;
    #pragma unroll 4
    for (int k = ky * 64; k < ky * 64 + 64; k++)
        acc += wr[k] * sW[(long)k * N + n];
    red[ky][tx] = acc;
    __syncthreads();
    if (ky == 0) {
        float s = sb[n];
        #pragma unroll
        for (int i = 0; i < 8; i++) s += red[i][tx];
        out[bidx * N + n] = s;
    }
}

// ---------------- fused prep: weights + ln1 + S1 + S2 + SS -------------------
__global__ __launch_bounds__(256) void prep_all_kernel(
    const float* __restrict__ x,
    const float* __restrict__ w,
    const float* __restrict__ ln1g, const float* __restrict__ ln1b,
    const float* __restrict__ g1W, const float* __restrict__ g1b,
    const float* __restrict__ g2W, const float* __restrict__ g2b,
    const float* __restrict__ gsW, const float* __restrict__ gsb,
    const float* __restrict__ r1W, const float* __restrict__ r1b,
    const float* __restrict__ m1W, const float* __restrict__ m2W,
    const float* __restrict__ msW, const float* __restrict__ r2W,
    const float* __restrict__ s1W, const float* __restrict__ s1b,
    const float* __restrict__ s2W, const float* __restrict__ s2b,
    const float* __restrict__ ssW, const float* __restrict__ ssb,
    bf16* __restrict__ Wh, bf16* __restrict__ Wl, float* __restrict__ BI,
    float* __restrict__ XLN, bf16* __restrict__ XLNh, bf16* __restrict__ XLNl,
    float* __restrict__ S1, float* __restrict__ S2, float* __restrict__ SS)
{
    __shared__ float red[8][33];
    int blk = blockIdx.x;
    if (blk < NB_W) {
        long i = (long)blk * 256 + threadIdx.x;
        if (i < NG) { prep_pack(g1W, g1b, Wh+OFF_G12, Wl+OFF_G12, BI+BI_G12, i, CC, 1536, 0); return; }
        i -= NG;
        if (i < NG) { prep_pack(g2W, g2b, Wh+OFF_G12, Wl+OFF_G12, BI+BI_G12, i, CC, 1536, CC); return; }
        i -= NG;
        if (i < NGS){ prep_pack(gsW, gsb, Wh+OFF_GS,  Wl+OFF_GS,  BI+BI_GS,  i, CD, CD, 0); return; }
        i -= NGS;
        if (i < NG) { prep_pack(r1W, r1b, Wh+OFF_R1,  Wl+OFF_R1,  BI+BI_R1,  i, CC, CC, 0); return; }
        i -= NG;
        if (i < NM) { prep_cvt(m1W, Wh+OFF_M1, Wl+OFF_M1, i); return; }
        i -= NM;
        if (i < NM) { prep_cvt(m2W, Wh+OFF_M2, Wl+OFF_M2, i); return; }
        i -= NM;
        if (i < NMS){ prep_cvt(msW, Wh+OFF_MS, Wl+OFF_MS, i); return; }
        i -= NMS;
        prep_cvt(r2W, Wh+OFF_R2, Wl+OFF_R2, i);
        return;
    }
    blk -= NB_W;
    if (blk < NB_LN) {
        ln_row_body(x, ln1g, ln1b, XLN, XLNh, XLNl, blk, red);
        return;
    }
    blk -= NB_LN;
    if (blk < NB_S1) { style_body(w, s1W, s1b, S1, 0, TD, blk, red); return; }
    blk -= NB_S1;
    if (blk < NB_S1) { style_body(w, s2W, s2b, S2, 0, TD, blk, red); return; }
    blk -= NB_S1;
    style_body(w, ssW, ssb, SS, 1, CD/2, blk, red);
}

// ---------------- tiled transpose + split: (b,t,d) fp32 -> (b,d,t) hi/lo -----
__global__ void trans_split_kernel(const float* __restrict__ in,
                                   bf16* __restrict__ oh,
                                   bf16* __restrict__ ol, int R, int C) {
    __shared__ float tile[32][33];
    long zo = (long)blockIdx.z * R * C;
    in += zo; oh += zo; ol += zo;
    int r0 = blockIdx.y * 32, c0 = blockIdx.x * 32;
    for (int i = threadIdx.y; i < 32; i += 8)
        tile[i][threadIdx.x] = in[(long)(r0 + i) * C + c0 + threadIdx.x];
    __syncthreads();
    for (int i = threadIdx.y; i < 32; i += 8) {
        float v = tile[threadIdx.x][i];
        bf16 h, l;
        split_bf16(v, h, l);
        long o = (long)(c0 + i) * R + r0 + threadIdx.x;
        oh[o] = h;
        ol[o] = l;
    }
}

// ---------------- bf16x3 mma.sync GEMM (frozen round-8 mainloop) -------------
// C(M,N) = (Ah+Al)(M,K) @ (Bh+Bl)(K,N)  (lo*lo dropped)
// A k-contig (lda), B n-contig (ldb). CTA 128x128x32, 128 thr, 4 warps 2x2,
// warp tile 64x64. 3-stage cp.async pipeline.
// M12: blockIdx.z picks (A,bias,epilogue): z=0 -> fp32 Cf; z=1 -> Ah2/bias2 -> split Ch/Cl.
#define ASTR 40
#define BSTR 136
#define A_BYTES (128 * ASTR * 2)
#define B_BYTES (32 * BSTR * 2)
#define STAGEB  (2 * A_BYTES + 2 * B_BYTES)   // 37888
#define SMEMB   (3 * STAGEB)                  // 113664

template <bool GLU, bool GLUPAIR, bool GELU, bool SPLIT, bool FP32O, bool M12>
__global__ __launch_bounds__(128) void gemm_v7(
    const bf16* __restrict__ Ah, const bf16* __restrict__ Al,
    const bf16* __restrict__ Ah2, const bf16* __restrict__ Al2,
    const bf16* __restrict__ Bh, const bf16* __restrict__ Bl,
    const float* __restrict__ bias, const float* __restrict__ bias2,
    const float* __restrict__ styleS, const float* __restrict__ styleS2,
    const float* __restrict__ res,
    float* __restrict__ Cf, bf16* __restrict__ Ch, bf16* __restrict__ Cl,
    bf16* __restrict__ Ch2, bf16* __restrict__ Cl2,
    int N, int K, int lda, int ldb,
    long sA, long sB, long sC, long sRes)
{
    extern __shared__ char smem[];

    const int z = blockIdx.z;
    const bf16* Agh;
    const bf16* Agl;
    if (M12 && z) { Agh = Ah2; Agl = Al2; }
    else          { Agh = Ah + (long)z * sA; Agl = Al + (long)z * sA; }
    const float* biasp = (M12 && z) ? bias2 : bias;
    const bf16* Bgh = Bh + (long)z * sB;
    const bf16* Bgl = Bl + (long)z * sB;
    const float* resp = res ? res + (long)z * sRes : nullptr;

    const int m0 = blockIdx.y * 128, n0 = blockIdx.x * 128;
    const int tid = threadIdx.x;
    const int lane = tid & 31, wid = tid >> 5;
    const int wm = wid >> 1, wn = wid & 1;
    const int lr = lane >> 2, lc = lane & 3;

    const int aoffL = (lane & 15) * ASTR + ((lane >> 4) << 3);
    const int boffC = ((lane >> 4) << 3);

    float acc[4][8][4];
    #pragma unroll
    for (int i = 0; i < 4; i++)
        #pragma unroll
        for (int j = 0; j < 8; j++) {
            acc[i][j][0] = 0.f; acc[i][j][1] = 0.f;
            acc[i][j][2] = 0.f; acc[i][j][3] = 0.f;
        }

    auto loadStage = [&](int st, int k0) {
        char* base = smem + st * STAGEB;
        bf16* ah = (bf16*)(base);
        bf16* al = (bf16*)(base + A_BYTES);
        bf16* bh = (bf16*)(base + 2 * A_BYTES);
        bf16* bl = (bf16*)(base + 2 * A_BYTES + B_BYTES);
        #pragma unroll
        for (int i = tid; i < 512; i += 128) {
            const int r = i >> 2, c = i & 3;
            const long go = (long)(m0 + r) * lda + k0 + c * 8;
            const int so = r * ASTR + c * 8;
            cp16(ah + so, Agh + go);
            cp16(al + so, Agl + go);
        }
        #pragma unroll
        for (int i = tid; i < 512; i += 128) {
            const int r = i >> 4, c = i & 15;
            const long go = (long)(k0 + r) * ldb + n0 + c * 8;
            const int so = r * BSTR + c * 8;
            cp16(bh + so, Bgh + go);
            cp16(bl + so, Bgl + go);
        }
        cp_commit();
    };

    const int NST = K >> 5;
    loadStage(0, 0);
    if (NST > 1) loadStage(1, 32);

    for (int it = 0; it < NST; it++) {
        const int st = it % 3;
        if (it + 2 <= NST) asm volatile("cp.async.wait_group 1;" ::: "memory");
        else               asm volatile("cp.async.wait_group 0;" ::: "memory");
        __syncthreads();

        char* base = smem + st * STAGEB;
        const bf16* ah = (const bf16*)(base);
        const bf16* al = (const bf16*)(base + A_BYTES);
        const bf16* bh = (const bf16*)(base + 2 * A_BYTES);
        const bf16* bl = (const bf16*)(base + 2 * A_BYTES + B_BYTES);

        #pragma unroll
        for (int ks = 0; ks < 2; ks++) {
            uint32_t fAh[4][4], fAl[4][4];
            const int aoff = aoffL + ks * 16;
            #pragma unroll
            for (int mt = 0; mt < 4; mt++) {
                const int mb = (wm * 64 + mt * 16) * ASTR + aoff;
                ldsm4(fAh[mt], ah + mb);
                ldsm4(fAl[mt], al + mb);
            }
            const int brow = (ks * 16 + (lane & 15)) * BSTR + boffC;
            #pragma unroll
            for (int ph = 0; ph < 2; ph++) {
                uint32_t fBh[4][2], fBl[4][2];
                #pragma unroll
                for (int p = 0; p < 2; p++) {
                    const int nb = brow + wn * 64 + ph * 32 + p * 16;
                    uint32_t r[4];
                    ldsm4t(r, bh + nb);
                    fBh[2*p][0] = r[0]; fBh[2*p][1] = r[1];
                    fBh[2*p+1][0] = r[2]; fBh[2*p+1][1] = r[3];
                    ldsm4t(r, bl + nb);
                    fBl[2*p][0] = r[0]; fBl[2*p][1] = r[1];
                    fBl[2*p+1][0] = r[2]; fBl[2*p+1][1] = r[3];
                }
                #pragma unroll
                for (int mt = 0; mt < 4; mt++)
                    #pragma unroll
                    for (int nt = 0; nt < 4; nt++) {
                        float* a4 = acc[mt][ph * 4 + nt];
                        mma_bf16(a4, fAh[mt], fBh[nt]);
                        mma_bf16(a4, fAh[mt], fBl[nt]);
                        mma_bf16(a4, fAl[mt], fBh[nt]);
                    }
            }
        }
        if (it + 2 < NST) loadStage((it + 2) % 3, (it + 2) << 5);
    }

    // ---- epilogue ----
    #pragma unroll
    for (int mt = 0; mt < 4; mt++) {
        #pragma unroll
        for (int half = 0; half < 2; half++) {
            const int row = m0 + wm * 64 + mt * 16 + lr + half * 8;
            #pragma unroll
            for (int nt = 0; nt < 8; nt++) {
                const int col = n0 + wn * 64 + nt * 8 + 2 * lc;
                float v0 = acc[mt][nt][2 * half + 0];
                float v1 = acc[mt][nt][2 * half + 1];
                if (M12) {
                    v0 += biasp[col];
                    v1 += biasp[col + 1];
                    const long off = (long)row * N + col;
                    if (z == 0) {
                        *(float2*)&Cf[off] = make_float2(v0, v1);
                    } else {
                        bf16 h0, l0, h1, l1;
                        split_bf16(v0, h0, l0);
                        split_bf16(v1, h1, l1);
                        *(__nv_bfloat162*)(Ch + off) = __nv_bfloat162(h0, h1);
                        *(__nv_bfloat162*)(Cl + off) = __nv_bfloat162(l0, l1);
                    }
                } else if (GLU) {
                    v0 += biasp[col];
                    v1 += biasp[col + 1];
                    float gv = v0 / (1.f + __expf(-v1));
                    if (GLUPAIR) {
                        const bool sec = col >= CC;
                        const int j = (sec ? col - CC : col) >> 1;
                        const float* st = sec ? styleS2 : styleS;
                        gv *= st[(row >> 11) * TD + j];
                        bf16 h, l;
                        split_bf16(gv, h, l);
                        const long o = (long)row * TD + j;
                        if (sec) { Ch2[o] = h; Cl2[o] = l; }
                        else     { Ch[o]  = h; Cl[o]  = l; }
                    } else {
                        const int j = col >> 1;
                        if (styleS) gv *= styleS[(row >> 11) * (N >> 1) + j];
                        bf16 h, l;
                        split_bf16(gv, h, l);
                        const long o = (long)row * (N >> 1) + j;
                        Ch[o] = h;
                        Cl[o] = l;
                    }
                } else {
                    if (biasp) { v0 += biasp[col]; v1 += biasp[col + 1]; }
                    const long off = (long)row * N + col;
                    if (resp) {
                        float2 rv = *(const float2*)&resp[off];
                        v0 += rv.x; v1 += rv.y;
                    }
                    if (GELU) { v0 = gelu_f(v0); v1 = gelu_f(v1); }
                    if (FP32O) {
                        *(float2*)&Cf[(long)z * sC + off] = make_float2(v0, v1);
                    }
                    if (SPLIT) {
                        bf16 h0, l0, h1, l1;
                        split_bf16(v0, h0, l0);
                        split_bf16(v1, h1, l1);
                        const long o = (long)z * sC + off;
                        *(__nv_bfloat162*)(Ch + o) = __nv_bfloat162(h0, h1);
                        *(__nv_bfloat162*)(Cl + o) = __nv_bfloat162(l0, l1);
                    }
                }
            }
        }
    }
}

// ---------------- host side --------------------------------------------------
static void* symp(const void* s) {
    void* p = nullptr;
    cudaGetSymbolAddress(&p, s);
    return p;
}

extern "C" void kernel_launch(void* const* d_in, const int* in_sizes, int n_in,
                              void* d_out, int out_size) {
    const float* x     = (const float*)d_in[0];
    const float* w     = (const float*)d_in[1];
    const float* ln1_g = (const float*)d_in[2];
    const float* ln1_b = (const float*)d_in[3];
    const float* ln2_g = (const float*)d_in[4];
    const float* ln2_b = (const float*)d_in[5];
    const float* g1_W  = (const float*)d_in[6];
    const float* g1_b  = (const float*)d_in[7];
    const float* s1_W  = (const float*)d_in[8];
    const float* s1_b  = (const float*)d_in[9];
    const float* m1_W  = (const float*)d_in[10];
    const float* m1_b  = (const float*)d_in[11];
    const float* g2_W  = (const float*)d_in[12];
    const float* g2_b  = (const float*)d_in[13];
    const float* s2_W  = (const float*)d_in[14];
    const float* s2_b  = (const float*)d_in[15];
    const float* m2_W  = (const float*)d_in[16];
    const float* m2_b  = (const float*)d_in[17];
    const float* gs_W  = (const float*)d_in[18];
    const float* gs_b  = (const float*)d_in[19];
    const float* ss_W  = (const float*)d_in[20];
    const float* ss_b  = (const float*)d_in[21];
    const float* ms_W  = (const float*)d_in[22];
    const float* ms_b  = (const float*)d_in[23];
    const float* r1_W  = (const float*)d_in[24];
    const float* r1_b  = (const float*)d_in[25];
    const float* r2_W  = (const float*)d_in[26];
    const float* r2_b  = (const float*)d_in[27];

    float* XLN = (float*)symp(BUF_XLN);
    float* X2  = (float*)symp(BUF_X2);
    float* H1F = (float*)symp(BUF_H1F);
    float* S1  = (float*)symp(BUF_S1);
    float* S2  = (float*)symp(BUF_S2);
    float* SS  = (float*)symp(BUF_SS);
    float* BI  = (float*)symp(BUF_BI);
    bf16* XLNh = (bf16*)symp(S_XLNh);  bf16* XLNl = (bf16*)symp(S_XLNl);
    bf16* ACTh = (bf16*)symp(S_ACTh);  bf16* ACTl = (bf16*)symp(S_ACTl);
    bf16* A1h  = (bf16*)symp(S_A1h);   bf16* A1l  = (bf16*)symp(S_A1l);
    bf16* A2h  = (bf16*)symp(S_A2h);   bf16* A2l  = (bf16*)symp(S_A2l);
    bf16* H1h  = (bf16*)symp(S_H1h);   bf16* H1l  = (bf16*)symp(S_H1l);
    bf16* H2h  = (bf16*)symp(S_H2h);   bf16* H2l  = (bf16*)symp(S_H2l);
    bf16* MIXh = (bf16*)symp(S_MIXh);  bf16* MIXl = (bf16*)symp(S_MIXl);
    bf16* X3h  = (bf16*)symp(S_X3h);   bf16* X3l  = (bf16*)symp(S_X3l);
    bf16* Wh   = (bf16*)symp(S_Wh);    bf16* Wl   = (bf16*)symp(S_Wl);
    float* OUT = (float*)d_out;

    // dynamic smem opt-in (idempotent)
    cudaFuncSetAttribute(gemm_v7<true,  true,  false, false, false, false>,
                         cudaFuncAttributeMaxDynamicSharedMemorySize, SMEMB);
    cudaFuncSetAttribute(gemm_v7<true,  false, false, false, false, false>,
                         cudaFuncAttributeMaxDynamicSharedMemorySize, SMEMB);
    cudaFuncSetAttribute(gemm_v7<false, false, false, true,  false, false>,
                         cudaFuncAttributeMaxDynamicSharedMemorySize, SMEMB);
    cudaFuncSetAttribute(gemm_v7<false, false, true,  true,  false, false>,
                         cudaFuncAttributeMaxDynamicSharedMemorySize, SMEMB);
    cudaFuncSetAttribute(gemm_v7<false, false, false, false, true,  false>,
                         cudaFuncAttributeMaxDynamicSharedMemorySize, SMEMB);
    cudaFuncSetAttribute(gemm_v7<false, false, false, false, false, true>,
                         cudaFuncAttributeMaxDynamicSharedMemorySize, SMEMB);

    // 1) fused prep: weights + ln1 + S1 + S2 + SS (single launch)
    prep_all_kernel<<<NB_ALL, 256>>>(
        x, w, ln1_g, ln1_b,
        g1_W, g1_b, g2_W, g2_b, gs_W, gs_b, r1_W, r1_b,
        m1_W, m2_W, ms_W, r2_W,
        s1_W, s1_b, s2_W, s2_b, ss_W, ss_b,
        Wh, Wl, BI, XLN, XLNh, XLNl, S1, S2, SS);
    // 2) fused GLU1|GLU2 GEMM -> A1, A2
    gemm_v7<true, true, false, false, false, false>
        <<<dim3(1536/128, ROWS/128, 1), 128, SMEMB>>>(
        XLNh, XLNl, nullptr, nullptr, Wh+OFF_G12, Wl+OFF_G12,
        BI+BI_G12, nullptr, S1, S2, nullptr,
        nullptr, A1h, A1l, A2h, A2l, 1536, CC, CC, 1536, 0, 0, 0, 0);
    // 3) merged m1|m2 GEMM: z=0 -> H1F fp32 = A1@M1+b1 ; z=1 -> H2 split = A2@M2+b2
    gemm_v7<false, false, false, false, false, true>
        <<<dim3(TD/128, ROWS/128, 2), 128, SMEMB>>>(
        A1h, A1l, A2h, A2l, Wh+OFF_M1, Wl+OFF_M1,
        m1_b, m2_b, nullptr, nullptr, nullptr,
        H1F, H2h, H2l, nullptr, nullptr, TD, TD, TD, TD, 0, NM, 0, 0);
    // 4) H1 (b,d,t) hi/lo via coalesced transpose+split
    trans_split_kernel<<<dim3(TD/32, TT/32, BB), dim3(32, 8)>>>(H1F, H1h, H1l, TT, TD);
    // 5) mix[b,d,c] = gelu(sum_t H1[b,d,t] * XLN[b,t,c])   M=TD, N=CC, K=TT
    gemm_v7<false, false, true, true, false, false>
        <<<dim3(CC/128, TD/128, BB), 128, SMEMB>>>(
        H1h, H1l, nullptr, nullptr, XLNh, XLNl,
        nullptr, nullptr, nullptr, nullptr, nullptr,
        nullptr, MIXh, MIXl, nullptr, nullptr, CC, TT, TT, CC,
        (long)TD*TT, (long)TT*CC, (long)TD*CC, 0);
    // 6) x2[b,t,c] = sum_d H2[b,t,d] * MIX[b,d,c] + xln    M=TT, N=CC, K=TD
    gemm_v7<false, false, false, false, true, false>
        <<<dim3(CC/128, TT/128, BB), 128, SMEMB>>>(
        H2h, H2l, nullptr, nullptr, MIXh, MIXl,
        nullptr, nullptr, nullptr, nullptr, XLN,
        X2, nullptr, nullptr, nullptr, nullptr, CC, TD, TD, CC,
        (long)TT*TD, (long)TD*CC, (long)TT*CC, (long)TT*CC);
    // 7) ln2
    ln_split_kernel<<<ROWS, 256>>>(X2, ln2_g, ln2_b, nullptr, XLNh, XLNl);
    // 8) GLUs GEMM -> ACT
    gemm_v7<true, false, false, false, false, false>
        <<<dim3(CD/128, ROWS/128, 1), 128, SMEMB>>>(
        XLNh, XLNl, nullptr, nullptr, Wh+OFF_GS, Wl+OFF_GS,
        BI+BI_GS, nullptr, SS, nullptr, nullptr,
        nullptr, ACTh, ACTl, nullptr, nullptr, CD, CC, CC, CD, 0, 0, 0, 0);
    // 9) X3 = ACT@MS + ms_b + X2 (split)
    gemm_v7<false, false, false, true, false, false>
        <<<dim3(CC/128, ROWS/128, 1), 128, SMEMB>>>(
        ACTh, ACTl, nullptr, nullptr, Wh+OFF_MS, Wl+OFF_MS,
        ms_b, nullptr, nullptr, nullptr, X2,
        nullptr, X3h, X3l, nullptr, nullptr, CC, CD/2, CD/2, CC, 0, 0, 0, 0);
    // 10) head GLU GEMM -> A1
    gemm_v7<true, false, false, false, false, false>
        <<<dim3(CC/128, ROWS/128, 1), 128, SMEMB>>>(
        X3h, X3l, nullptr, nullptr, Wh+OFF_R1, Wl+OFF_R1,
        BI+BI_R1, nullptr, nullptr, nullptr, nullptr,
        nullptr, A1h, A1l, nullptr, nullptr, CC, CC, CC, CC, 0, 0, 0, 0);
    // 11) OUT = A1@R2 + b
    gemm_v7<false, false, false, false, true, false>
        <<<dim3(CC/128, ROWS/128, 1), 128, SMEMB>>>(
        A1h, A1l, nullptr, nullptr, Wh+OFF_R2, Wl+OFF_R2,
        r2_b, nullptr, nullptr, nullptr, nullptr,
        OUT, nullptr, nullptr, nullptr, nullptr, CC, TD, TD, CC, 0, 0, 0, 0);
}

// round 15
// speedup vs baseline: 1.2392x; 1.0051x over previous
#include <cuda_runtime.h>
#include <cuda_bf16.h>
#include <cstdint>

// Shapes (fixed per problem)
#define BB 8
#define TT 2048
#define CC 768
#define WDIM 512
#define TD 384
#define CD 3072
#define ROWS (BB * TT)          // 16384

// weight pack offsets (elements), layout (K, N) n-contiguous
#define OFF_G12 0               // fused g1|g2, (768, 1536)
#define OFF_M1 1179648
#define OFF_M2 1327104
#define OFF_GS 1474560
#define OFF_MS 3833856
#define OFF_R1 5013504
#define OFF_R2 5603328
#define WTOT   5898240

// bias pack offsets
#define BI_G12 0
#define BI_GS  1536
#define BI_R1  (1536 + CD)

// region sizes for fused weight prep
#define NG  (CC * CC)           // 589824
#define NGS (CC * CD)           // 2359296
#define NM  (TD * TD)           // 147456
#define NMS ((CD/2) * CC)       // 1179648
#define NR2 (TD * CC)           // 294912

// prep_all grid regions (blocks of 256 threads)
#define NB_W  (WTOT / 256)          // 23040
#define NB_LN ROWS                  // 16384
#define NB_S1 ((TD / 32) * BB)      // 96
#define NB_SS (((CD/2) / 32) * BB)  // 384
#define NB_ALL (NB_W + NB_LN + 2 * NB_S1 + NB_SS)   // 40000

typedef __nv_bfloat16 bf16;

// ---------------- scratch (device globals; no allocation allowed) ----------
__device__ float BUF_XLN[ROWS * CC];
__device__ float BUF_X2 [ROWS * CC];
__device__ float BUF_S1 [BB * TD];
__device__ float BUF_S2 [BB * TD];
__device__ float BUF_SS [BB * (CD/2)];
__device__ float BUF_BI [1536 + CD + CC];

__device__ bf16 S_XLNh[ROWS * CC],      S_XLNl[ROWS * CC];
__device__ bf16 S_ACTh[ROWS * (CD/2)],  S_ACTl[ROWS * (CD/2)];
__device__ bf16 S_A1h [ROWS * TD],      S_A1l [ROWS * TD];
__device__ bf16 S_A2h [ROWS * TD],      S_A2l [ROWS * TD];
__device__ bf16 S_H1h [BB * TD * TT],   S_H1l [BB * TD * TT];   // (b,d,t)
__device__ bf16 S_H2h [ROWS * TD],      S_H2l [ROWS * TD];      // (b,t,d)
__device__ bf16 S_MIXh[BB * TD * CC],   S_MIXl[BB * TD * CC];   // (b,d,c)
__device__ bf16 S_X3h [ROWS * CC],      S_X3l [ROWS * CC];
__device__ bf16 S_Wh  [WTOT],           S_Wl  [WTOT];

// ---------------- helpers ---------------------------------------------------
__device__ __forceinline__ float gelu_f(float v) {
    return 0.5f * v * (1.0f + erff(v * 0.70710678118654752f));
}
__device__ __forceinline__ void split_bf16(float v, bf16& h, bf16& l) {
    h = __float2bfloat16_rn(v);
    l = __float2bfloat16_rn(v - __bfloat162float(h));
}
__device__ __forceinline__ void cp16(void* smem, const void* gmem) {
    uint32_t s = (uint32_t)__cvta_generic_to_shared(smem);
    asm volatile("cp.async.cg.shared.global [%0], [%1], 16;" :: "r"(s), "l"(gmem));
}
__device__ __forceinline__ void cp_commit() { asm volatile("cp.async.commit_group;"); }

__device__ __forceinline__ void ldsm4(uint32_t* r, const void* p) {
    uint32_t a = (uint32_t)__cvta_generic_to_shared(p);
    asm volatile("ldmatrix.sync.aligned.m8n8.x4.shared.b16 {%0,%1,%2,%3}, [%4];"
                 : "=r"(r[0]), "=r"(r[1]), "=r"(r[2]), "=r"(r[3]) : "r"(a));
}
__device__ __forceinline__ void ldsm4t(uint32_t* r, const void* p) {
    uint32_t a = (uint32_t)__cvta_generic_to_shared(p);
    asm volatile("ldmatrix.sync.aligned.m8n8.x4.trans.shared.b16 {%0,%1,%2,%3}, [%4];"
                 : "=r"(r[0]), "=r"(r[1]), "=r"(r[2]), "=r"(r[3]) : "r"(a));
}
__device__ __forceinline__ void mma_bf16(float* d, const uint32_t* a, const uint32_t* b) {
    asm volatile(
        "mma.sync.aligned.m16n8k16.row.col.f32.bf16.bf16.f32 "
        "{%0,%1,%2,%3}, {%4,%5,%6,%7}, {%8,%9}, {%0,%1,%2,%3};"
        : "+f"(d[0]), "+f"(d[1]), "+f"(d[2]), "+f"(d[3])
        : "r"(a[0]), "r"(a[1]), "r"(a[2]), "r"(a[3]), "r"(b[0]), "r"(b[1]));
}

// ---------------- LayerNorm body (shared by prep_all and ln2) ---------------
__device__ __forceinline__ void ln_row_body(
    const float* __restrict__ x, const float* __restrict__ g,
    const float* __restrict__ b, float* __restrict__ yf,
    bf16* __restrict__ yh, bf16* __restrict__ yl,
    long row, float (*red)[33])
{
    const float* xr = x + row * CC;
    float s = 0.f, s2 = 0.f;
    for (int c = threadIdx.x; c < CC; c += 256) {
        float v = xr[c];
        s += v; s2 += v * v;
    }
    #pragma unroll
    for (int o = 16; o; o >>= 1) {
        s  += __shfl_xor_sync(0xFFFFFFFFu, s,  o);
        s2 += __shfl_xor_sync(0xFFFFFFFFu, s2, o);
    }
    int w = threadIdx.x >> 5, l = threadIdx.x & 31;
    if (l == 0) { red[0][w] = s; red[1][w] = s2; }
    __syncthreads();
    if (threadIdx.x < 32) {
        s  = (l < 8) ? red[0][l] : 0.f;
        s2 = (l < 8) ? red[1][l] : 0.f;
        #pragma unroll
        for (int o = 4; o; o >>= 1) {
            s  += __shfl_xor_sync(0xFFFFFFFFu, s,  o);
            s2 += __shfl_xor_sync(0xFFFFFFFFu, s2, o);
        }
        if (l == 0) { red[0][0] = s; red[1][0] = s2; }
    }
    __syncthreads();
    float mu  = red[0][0] / CC;
    float var = red[1][0] / CC - mu * mu;
    float inv = rsqrtf(var + 1e-6f);
    for (int c = threadIdx.x; c < CC; c += 256) {
        float v = (xr[c] - mu) * inv * g[c] + b[c];
        if (yf) yf[row * CC + c] = v;
        bf16 h, lo;
        split_bf16(v, h, lo);
        yh[row * CC + c] = h;
        yl[row * CC + c] = lo;
    }
}

__global__ void ln_split_kernel(const float* __restrict__ x,
                                const float* __restrict__ g,
                                const float* __restrict__ b,
                                float* __restrict__ yf,
                                bf16* __restrict__ yh,
                                bf16* __restrict__ yl) {
    __shared__ float red[8][33];
    ln_row_body(x, g, b, yf, yh, yl, blockIdx.x, red);
}

// ---------------- weight prep pieces -----------------------------------------
__device__ __forceinline__ void prep_pack(const float* W, const float* b,
                                          bf16* oh, bf16* ol, float* biasI,
                                          long i, int H, int ld, int coloff) {
    long k = i / H;
    int  n = (int)(i - k * H);
    int  src = (n & 1) ? (n >> 1) + (H >> 1) : (n >> 1);
    bf16 h, l;
    split_bf16(W[k * H + src], h, l);
    const long o = k * ld + coloff + n;
    oh[o] = h;
    ol[o] = l;
    if (k == 0) biasI[coloff + n] = b[src];
}
__device__ __forceinline__ void prep_cvt(const float* W, bf16* oh, bf16* ol, long i) {
    bf16 h, l;
    split_bf16(W[i], h, l);
    oh[i] = h;
    ol[i] = l;
}

// ---------------- style body: 32 cols x 8 k-slices of 64 ---------------------
__device__ __forceinline__ void style_body(
    const float* __restrict__ w, const float* __restrict__ sW,
    const float* __restrict__ sb, float* __restrict__ out,
    int sel, int N, int rblk, float (*red)[33])
{
    const int nb = N / 32;
    const int bidx = rblk / nb;
    const int nblk = rblk - bidx * nb;
    const int tx = threadIdx.x & 31, ky = threadIdx.x >> 5;
    const int n = nblk * 32 + tx;
    const float* wr = w + bidx * (2 * WDIM) + sel * WDIM;
    float acc = 0.f;
    #pragma unroll 4
    for (int k = ky * 64; k < ky * 64 + 64; k++)
        acc += wr[k] * sW[(long)k * N + n];
    red[ky][tx] = acc;
    __syncthreads();
    if (ky == 0) {
        float s = sb[n];
        #pragma unroll
        for (int i = 0; i < 8; i++) s += red[i][tx];
        out[bidx * N + n] = s;
    }
}

// ---------------- fused prep: weights + ln1 + S1 + S2 + SS -------------------
__global__ __launch_bounds__(256) void prep_all_kernel(
    const float* __restrict__ x,
    const float* __restrict__ w,
    const float* __restrict__ ln1g, const float* __restrict__ ln1b,
    const float* __restrict__ g1W, const float* __restrict__ g1b,
    const float* __restrict__ g2W, const float* __restrict__ g2b,
    const float* __restrict__ gsW, const float* __restrict__ gsb,
    const float* __restrict__ r1W, const float* __restrict__ r1b,
    const float* __restrict__ m1W, const float* __restrict__ m2W,
    const float* __restrict__ msW, const float* __restrict__ r2W,
    const float* __restrict__ s1W, const float* __restrict__ s1b,
    const float* __restrict__ s2W, const float* __restrict__ s2b,
    const float* __restrict__ ssW, const float* __restrict__ ssb,
    bf16* __restrict__ Wh, bf16* __restrict__ Wl, float* __restrict__ BI,
    float* __restrict__ XLN, bf16* __restrict__ XLNh, bf16* __restrict__ XLNl,
    float* __restrict__ S1, float* __restrict__ S2, float* __restrict__ SS)
{
    __shared__ float red[8][33];
    int blk = blockIdx.x;
    if (blk < NB_W) {
        long i = (long)blk * 256 + threadIdx.x;
        if (i < NG) { prep_pack(g1W, g1b, Wh+OFF_G12, Wl+OFF_G12, BI+BI_G12, i, CC, 1536, 0); return; }
        i -= NG;
        if (i < NG) { prep_pack(g2W, g2b, Wh+OFF_G12, Wl+OFF_G12, BI+BI_G12, i, CC, 1536, CC); return; }
        i -= NG;
        if (i < NGS){ prep_pack(gsW, gsb, Wh+OFF_GS,  Wl+OFF_GS,  BI+BI_GS,  i, CD, CD, 0); return; }
        i -= NGS;
        if (i < NG) { prep_pack(r1W, r1b, Wh+OFF_R1,  Wl+OFF_R1,  BI+BI_R1,  i, CC, CC, 0); return; }
        i -= NG;
        if (i < NM) { prep_cvt(m1W, Wh+OFF_M1, Wl+OFF_M1, i); return; }
        i -= NM;
        if (i < NM) { prep_cvt(m2W, Wh+OFF_M2, Wl+OFF_M2, i); return; }
        i -= NM;
        if (i < NMS){ prep_cvt(msW, Wh+OFF_MS, Wl+OFF_MS, i); return; }
        i -= NMS;
        prep_cvt(r2W, Wh+OFF_R2, Wl+OFF_R2, i);
        return;
    }
    blk -= NB_W;
    if (blk < NB_LN) {
        ln_row_body(x, ln1g, ln1b, XLN, XLNh, XLNl, blk, red);
        return;
    }
    blk -= NB_LN;
    if (blk < NB_S1) { style_body(w, s1W, s1b, S1, 0, TD, blk, red); return; }
    blk -= NB_S1;
    if (blk < NB_S1) { style_body(w, s2W, s2b, S2, 0, TD, blk, red); return; }
    blk -= NB_S1;
    style_body(w, ssW, ssb, SS, 1, CD/2, blk, red);
}

// ---------------- bf16x3 mma.sync GEMM (frozen round-8 mainloop) -------------
// C(M,N) = (Ah+Al)(M,K) @ (Bh+Bl)(K,N)  (lo*lo dropped)
// A k-contig (lda), B n-contig (ldb). CTA 128x128x32, 128 thr, 4 warps 2x2,
// warp tile 64x64. 3-stage cp.async pipeline.
// M12: blockIdx.z picks branch:
//   z=0: A1@M1+b1, epilogue = smem-staged transpose -> H1 (b,d,t) split (Ch/Cl)
//   z=1: A2@M2+b2, epilogue = row-major split -> H2 (b,t,d) (Ch2/Cl2)
#define ASTR 40
#define BSTR 136
#define A_BYTES (128 * ASTR * 2)
#define B_BYTES (32 * BSTR * 2)
#define STAGEB  (2 * A_BYTES + 2 * B_BYTES)   // 37888
#define SMEMB   (3 * STAGEB)                  // 113664

template <bool GLU, bool GLUPAIR, bool GELU, bool SPLIT, bool FP32O, bool M12>
__global__ __launch_bounds__(128) void gemm_v8(
    const bf16* __restrict__ Ah, const bf16* __restrict__ Al,
    const bf16* __restrict__ Ah2, const bf16* __restrict__ Al2,
    const bf16* __restrict__ Bh, const bf16* __restrict__ Bl,
    const float* __restrict__ bias, const float* __restrict__ bias2,
    const float* __restrict__ styleS, const float* __restrict__ styleS2,
    const float* __restrict__ res,
    float* __restrict__ Cf, bf16* __restrict__ Ch, bf16* __restrict__ Cl,
    bf16* __restrict__ Ch2, bf16* __restrict__ Cl2,
    int N, int K, int lda, int ldb,
    long sA, long sB, long sC, long sRes)
{
    extern __shared__ char smem[];

    const int z = blockIdx.z;
    const bf16* Agh;
    const bf16* Agl;
    if (M12 && z) { Agh = Ah2; Agl = Al2; }
    else          { Agh = Ah + (long)z * sA; Agl = Al + (long)z * sA; }
    const float* biasp = (M12 && z) ? bias2 : bias;
    const bf16* Bgh = Bh + (long)z * sB;
    const bf16* Bgl = Bl + (long)z * sB;
    const float* resp = res ? res + (long)z * sRes : nullptr;

    const int m0 = blockIdx.y * 128, n0 = blockIdx.x * 128;
    const int tid = threadIdx.x;
    const int lane = tid & 31, wid = tid >> 5;
    const int wm = wid >> 1, wn = wid & 1;
    const int lr = lane >> 2, lc = lane & 3;

    const int aoffL = (lane & 15) * ASTR + ((lane >> 4) << 3);
    const int boffC = ((lane >> 4) << 3);

    float acc[4][8][4];
    #pragma unroll
    for (int i = 0; i < 4; i++)
        #pragma unroll
        for (int j = 0; j < 8; j++) {
            acc[i][j][0] = 0.f; acc[i][j][1] = 0.f;
            acc[i][j][2] = 0.f; acc[i][j][3] = 0.f;
        }

    auto loadStage = [&](int st, int k0) {
        char* base = smem + st * STAGEB;
        bf16* ah = (bf16*)(base);
        bf16* al = (bf16*)(base + A_BYTES);
        bf16* bh = (bf16*)(base + 2 * A_BYTES);
        bf16* bl = (bf16*)(base + 2 * A_BYTES + B_BYTES);
        #pragma unroll
        for (int i = tid; i < 512; i += 128) {
            const int r = i >> 2, c = i & 3;
            const long go = (long)(m0 + r) * lda + k0 + c * 8;
            const int so = r * ASTR + c * 8;
            cp16(ah + so, Agh + go);
            cp16(al + so, Agl + go);
        }
        #pragma unroll
        for (int i = tid; i < 512; i += 128) {
            const int r = i >> 4, c = i & 15;
            const long go = (long)(k0 + r) * ldb + n0 + c * 8;
            const int so = r * BSTR + c * 8;
            cp16(bh + so, Bgh + go);
            cp16(bl + so, Bgl + go);
        }
        cp_commit();
    };

    const int NST = K >> 5;
    loadStage(0, 0);
    if (NST > 1) loadStage(1, 32);

    for (int it = 0; it < NST; it++) {
        const int st = it % 3;
        if (it + 2 <= NST) asm volatile("cp.async.wait_group 1;" ::: "memory");
        else               asm volatile("cp.async.wait_group 0;" ::: "memory");
        __syncthreads();

        char* base = smem + st * STAGEB;
        const bf16* ah = (const bf16*)(base);
        const bf16* al = (const bf16*)(base + A_BYTES);
        const bf16* bh = (const bf16*)(base + 2 * A_BYTES);
        const bf16* bl = (const bf16*)(base + 2 * A_BYTES + B_BYTES);

        #pragma unroll
        for (int ks = 0; ks < 2; ks++) {
            uint32_t fAh[4][4], fAl[4][4];
            const int aoff = aoffL + ks * 16;
            #pragma unroll
            for (int mt = 0; mt < 4; mt++) {
                const int mb = (wm * 64 + mt * 16) * ASTR + aoff;
                ldsm4(fAh[mt], ah + mb);
                ldsm4(fAl[mt], al + mb);
            }
            const int brow = (ks * 16 + (lane & 15)) * BSTR + boffC;
            #pragma unroll
            for (int ph = 0; ph < 2; ph++) {
                uint32_t fBh[4][2], fBl[4][2];
                #pragma unroll
                for (int p = 0; p < 2; p++) {
                    const int nb = brow + wn * 64 + ph * 32 + p * 16;
                    uint32_t r[4];
                    ldsm4t(r, bh + nb);
                    fBh[2*p][0] = r[0]; fBh[2*p][1] = r[1];
                    fBh[2*p+1][0] = r[2]; fBh[2*p+1][1] = r[3];
                    ldsm4t(r, bl + nb);
                    fBl[2*p][0] = r[0]; fBl[2*p][1] = r[1];
                    fBl[2*p+1][0] = r[2]; fBl[2*p+1][1] = r[3];
                }
                #pragma unroll
                for (int mt = 0; mt < 4; mt++)
                    #pragma unroll
                    for (int nt = 0; nt < 4; nt++) {
                        float* a4 = acc[mt][ph * 4 + nt];
                        mma_bf16(a4, fAh[mt], fBh[nt]);
                        mma_bf16(a4, fAh[mt], fBl[nt]);
                        mma_bf16(a4, fAl[mt], fBh[nt]);
                    }
            }
        }
        if (it + 2 < NST) loadStage((it + 2) % 3, (it + 2) << 5);
    }

    // ---- epilogue ----
    if (M12 && z == 0) {
        // H1 path: stage C tile (fp32, +bias) into smem, transpose, split,
        // write H1 (b,d,t) with coalesced 64B warp stores.
        float (*T)[129] = (float(*)[129])smem;
        __syncthreads();                      // mainloop smem reads complete
        #pragma unroll
        for (int mt = 0; mt < 4; mt++) {
            #pragma unroll
            for (int half = 0; half < 2; half++) {
                const int rowl = wm * 64 + mt * 16 + lr + half * 8;
                #pragma unroll
                for (int nt = 0; nt < 8; nt++) {
                    const int coll = wn * 64 + nt * 8 + 2 * lc;
                    T[rowl][coll]     = acc[mt][nt][2 * half + 0] + biasp[n0 + coll];
                    T[rowl][coll + 1] = acc[mt][nt][2 * half + 1] + biasp[n0 + coll + 1];
                }
            }
        }
        __syncthreads();
        const int b  = m0 >> 11;
        const int tb = m0 & 2047;
        for (int dl = wid; dl < 128; dl += 4) {
            const long ob = ((long)b * TD + n0 + dl) * TT + tb;
            #pragma unroll
            for (int t0 = 0; t0 < 128; t0 += 32) {
                bf16 h, l;
                split_bf16(T[t0 + lane][dl], h, l);
                Ch[ob + t0 + lane] = h;
                Cl[ob + t0 + lane] = l;
            }
        }
    } else {
        #pragma unroll
        for (int mt = 0; mt < 4; mt++) {
            #pragma unroll
            for (int half = 0; half < 2; half++) {
                const int row = m0 + wm * 64 + mt * 16 + lr + half * 8;
                #pragma unroll
                for (int nt = 0; nt < 8; nt++) {
                    const int col = n0 + wn * 64 + nt * 8 + 2 * lc;
                    float v0 = acc[mt][nt][2 * half + 0];
                    float v1 = acc[mt][nt][2 * half + 1];
                    if (M12) {
                        // z == 1: H2 split, row-major (b,t,d)
                        v0 += biasp[col];
                        v1 += biasp[col + 1];
                        const long off = (long)row * N + col;
                        bf16 h0, l0, h1, l1;
                        split_bf16(v0, h0, l0);
                        split_bf16(v1, h1, l1);
                        *(__nv_bfloat162*)(Ch2 + off) = __nv_bfloat162(h0, h1);
                        *(__nv_bfloat162*)(Cl2 + off) = __nv_bfloat162(l0, l1);
                    } else if (GLU) {
                        v0 += biasp[col];
                        v1 += biasp[col + 1];
                        float gv = v0 / (1.f + __expf(-v1));
                        if (GLUPAIR) {
                            const bool sec = col >= CC;
                            const int j = (sec ? col - CC : col) >> 1;
                            const float* st = sec ? styleS2 : styleS;
                            gv *= st[(row >> 11) * TD + j];
                            bf16 h, l;
                            split_bf16(gv, h, l);
                            const long o = (long)row * TD + j;
                            if (sec) { Ch2[o] = h; Cl2[o] = l; }
                            else     { Ch[o]  = h; Cl[o]  = l; }
                        } else {
                            const int j = col >> 1;
                            if (styleS) gv *= styleS[(row >> 11) * (N >> 1) + j];
                            bf16 h, l;
                            split_bf16(gv, h, l);
                            const long o = (long)row * (N >> 1) + j;
                            Ch[o] = h;
                            Cl[o] = l;
                        }
                    } else {
                        if (biasp) { v0 += biasp[col]; v1 += biasp[col + 1]; }
                        const long off = (long)row * N + col;
                        if (resp) {
                            float2 rv = *(const float2*)&resp[off];
                            v0 += rv.x; v1 += rv.y;
                        }
                        if (GELU) { v0 = gelu_f(v0); v1 = gelu_f(v1); }
                        if (FP32O) {
                            *(float2*)&Cf[(long)z * sC + off] = make_float2(v0, v1);
                        }
                        if (SPLIT) {
                            bf16 h0, l0, h1, l1;
                            split_bf16(v0, h0, l0);
                            split_bf16(v1, h1, l1);
                            const long o = (long)z * sC + off;
                            *(__nv_bfloat162*)(Ch + o) = __nv_bfloat162(h0, h1);
                            *(__nv_bfloat162*)(Cl + o) = __nv_bfloat162(l0, l1);
                        }
                    }
                }
            }
        }
    }
}

// ---------------- host side --------------------------------------------------
static void* symp(const void* s) {
    void* p = nullptr;
    cudaGetSymbolAddress(&p, s);
    return p;
}

extern "C" void kernel_launch(void* const* d_in, const int* in_sizes, int n_in,
                              void* d_out, int out_size) {
    const float* x     = (const float*)d_in[0];
    const float* w     = (const float*)d_in[1];
    const float* ln1_g = (const float*)d_in[2];
    const float* ln1_b = (const float*)d_in[3];
    const float* ln2_g = (const float*)d_in[4];
    const float* ln2_b = (const float*)d_in[5];
    const float* g1_W  = (const float*)d_in[6];
    const float* g1_b  = (const float*)d_in[7];
    const float* s1_W  = (const float*)d_in[8];
    const float* s1_b  = (const float*)d_in[9];
    const float* m1_W  = (const float*)d_in[10];
    const float* m1_b  = (const float*)d_in[11];
    const float* g2_W  = (const float*)d_in[12];
    const float* g2_b  = (const float*)d_in[13];
    const float* s2_W  = (const float*)d_in[14];
    const float* s2_b  = (const float*)d_in[15];
    const float* m2_W  = (const float*)d_in[16];
    const float* m2_b  = (const float*)d_in[17];
    const float* gs_W  = (const float*)d_in[18];
    const float* gs_b  = (const float*)d_in[19];
    const float* ss_W  = (const float*)d_in[20];
    const float* ss_b  = (const float*)d_in[21];
    const float* ms_W  = (const float*)d_in[22];
    const float* ms_b  = (const float*)d_in[23];
    const float* r1_W  = (const float*)d_in[24];
    const float* r1_b  = (const float*)d_in[25];
    const float* r2_W  = (const float*)d_in[26];
    const float* r2_b  = (const float*)d_in[27];

    float* XLN = (float*)symp(BUF_XLN);
    float* X2  = (float*)symp(BUF_X2);
    float* S1  = (float*)symp(BUF_S1);
    float* S2  = (float*)symp(BUF_S2);
    float* SS  = (float*)symp(BUF_SS);
    float* BI  = (float*)symp(BUF_BI);
    bf16* XLNh = (bf16*)symp(S_XLNh);  bf16* XLNl = (bf16*)symp(S_XLNl);
    bf16* ACTh = (bf16*)symp(S_ACTh);  bf16* ACTl = (bf16*)symp(S_ACTl);
    bf16* A1h  = (bf16*)symp(S_A1h);   bf16* A1l  = (bf16*)symp(S_A1l);
    bf16* A2h  = (bf16*)symp(S_A2h);   bf16* A2l  = (bf16*)symp(S_A2l);
    bf16* H1h  = (bf16*)symp(S_H1h);   bf16* H1l  = (bf16*)symp(S_H1l);
    bf16* H2h  = (bf16*)symp(S_H2h);   bf16* H2l  = (bf16*)symp(S_H2l);
    bf16* MIXh = (bf16*)symp(S_MIXh);  bf16* MIXl = (bf16*)symp(S_MIXl);
    bf16* X3h  = (bf16*)symp(S_X3h);   bf16* X3l  = (bf16*)symp(S_X3l);
    bf16* Wh   = (bf16*)symp(S_Wh);    bf16* Wl   = (bf16*)symp(S_Wl);
    float* OUT = (float*)d_out;

    // dynamic smem opt-in (idempotent)
    cudaFuncSetAttribute(gemm_v8<true,  true,  false, false, false, false>,
                         cudaFuncAttributeMaxDynamicSharedMemorySize, SMEMB);
    cudaFuncSetAttribute(gemm_v8<true,  false, false, false, false, false>,
                         cudaFuncAttributeMaxDynamicSharedMemorySize, SMEMB);
    cudaFuncSetAttribute(gemm_v8<false, false, false, true,  false, false>,
                         cudaFuncAttributeMaxDynamicSharedMemorySize, SMEMB);
    cudaFuncSetAttribute(gemm_v8<false, false, true,  true,  false, false>,
                         cudaFuncAttributeMaxDynamicSharedMemorySize, SMEMB);
    cudaFuncSetAttribute(gemm_v8<false, false, false, false, true,  false>,
                         cudaFuncAttributeMaxDynamicSharedMemorySize, SMEMB);
    cudaFuncSetAttribute(gemm_v8<false, false, false, false, false, true>,
                         cudaFuncAttributeMaxDynamicSharedMemorySize, SMEMB);

    // 1) fused prep: weights + ln1 + S1 + S2 + SS (single launch)
    prep_all_kernel<<<NB_ALL, 256>>>(
        x, w, ln1_g, ln1_b,
        g1_W, g1_b, g2_W, g2_b, gs_W, gs_b, r1_W, r1_b,
        m1_W, m2_W, ms_W, r2_W,
        s1_W, s1_b, s2_W, s2_b, ss_W, ss_b,
        Wh, Wl, BI, XLN, XLNh, XLNl, S1, S2, SS);
    // 2) fused GLU1|GLU2 GEMM -> A1, A2
    gemm_v8<true, true, false, false, false, false>
        <<<dim3(1536/128, ROWS/128, 1), 128, SMEMB>>>(
        XLNh, XLNl, nullptr, nullptr, Wh+OFF_G12, Wl+OFF_G12,
        BI+BI_G12, nullptr, S1, S2, nullptr,
        nullptr, A1h, A1l, A2h, A2l, 1536, CC, CC, 1536, 0, 0, 0, 0);
    // 3) merged m1|m2 GEMM:
    //    z=0 -> H1 (b,d,t) split via fused epilogue transpose
    //    z=1 -> H2 (b,t,d) split
    gemm_v8<false, false, false, false, false, true>
        <<<dim3(TD/128, ROWS/128, 2), 128, SMEMB>>>(
        A1h, A1l, A2h, A2l, Wh+OFF_M1, Wl+OFF_M1,
        m1_b, m2_b, nullptr, nullptr, nullptr,
        nullptr, H1h, H1l, H2h, H2l, TD, TD, TD, TD, 0, NM, 0, 0);
    // 4) mix[b,d,c] = gelu(sum_t H1[b,d,t] * XLN[b,t,c])   M=TD, N=CC, K=TT
    gemm_v8<false, false, true, true, false, false>
        <<<dim3(CC/128, TD/128, BB), 128, SMEMB>>>(
        H1h, H1l, nullptr, nullptr, XLNh, XLNl,
        nullptr, nullptr, nullptr, nullptr, nullptr,
        nullptr, MIXh, MIXl, nullptr, nullptr, CC, TT, TT, CC,
        (long)TD*TT, (long)TT*CC, (long)TD*CC, 0);
    // 5) x2[b,t,c] = sum_d H2[b,t,d] * MIX[b,d,c] + xln    M=TT, N=CC, K=TD
    gemm_v8<false, false, false, false, true, false>
        <<<dim3(CC/128, TT/128, BB), 128, SMEMB>>>(
        H2h, H2l, nullptr, nullptr, MIXh, MIXl,
        nullptr, nullptr, nullptr, nullptr, XLN,
        X2, nullptr, nullptr, nullptr, nullptr, CC, TD, TD, CC,
        (long)TT*TD, (long)TD*CC, (long)TT*CC, (long)TT*CC);
    // 6) ln2
    ln_split_kernel<<<ROWS, 256>>>(X2, ln2_g, ln2_b, nullptr, XLNh, XLNl);
    // 7) GLUs GEMM -> ACT
    gemm_v8<true, false, false, false, false, false>
        <<<dim3(CD/128, ROWS/128, 1), 128, SMEMB>>>(
        XLNh, XLNl, nullptr, nullptr, Wh+OFF_GS, Wl+OFF_GS,
        BI+BI_GS, nullptr, SS, nullptr, nullptr,
        nullptr, ACTh, ACTl, nullptr, nullptr, CD, CC, CC, CD, 0, 0, 0, 0);
    // 8) X3 = ACT@MS + ms_b + X2 (split)
    gemm_v8<false, false, false, true, false, false>
        <<<dim3(CC/128, ROWS/128, 1), 128, SMEMB>>>(
        ACTh, ACTl, nullptr, nullptr, Wh+OFF_MS, Wl+OFF_MS,
        ms_b, nullptr, nullptr, nullptr, X2,
        nullptr, X3h, X3l, nullptr, nullptr, CC, CD/2, CD/2, CC, 0, 0, 0, 0);
    // 9) head GLU GEMM -> A1
    gemm_v8<true, false, false, false, false, false>
        <<<dim3(CC/128, ROWS/128, 1), 128, SMEMB>>>(
        X3h, X3l, nullptr, nullptr, Wh+OFF_R1, Wl+OFF_R1,
        BI+BI_R1, nullptr, nullptr, nullptr, nullptr,
        nullptr, A1h, A1l, nullptr, nullptr, CC, CC, CC, CC, 0, 0, 0, 0);
    // 10) OUT = A1@R2 + b
    gemm_v8<false, false, false, false, true, false>
        <<<dim3(CC/128, ROWS/128, 1), 128, SMEMB>>>(
        A1h, A1l, nullptr, nullptr, Wh+OFF_R2, Wl+OFF_R2,
        r2_b, nullptr, nullptr, nullptr, nullptr,
        OUT, nullptr, nullptr, nullptr, nullptr, CC, TD, TD, CC, 0, 0, 0, 0);
}